// round 9
// baseline (speedup 1.0000x reference)
#include <cuda_runtime.h>
#include <cstdint>

// ---------------------------------------------------------------------------
// Quantized LeNet, B=1024. Pipe-split strategy: legacy IMMA (tensor pipe) and
// dp4a (alu pipe) run CONCURRENTLY by partitioning each heavy kernel's grid
// into mma-blocks and dp4a-blocks. Pool-max commutes with monotone quant ->
// integer max first; quant chains precomputed into exact LUTs.
// ---------------------------------------------------------------------------

#define DEVBUF __device__ __align__(16)

__device__ unsigned g_absmax[4];                 // zero-init; atomicMax idempotent
DEVBUF int8_t g_w1q [32 * 9];                    // [oc][tap]
DEVBUF int8_t g_w2m [64 * 384];                  // conv2 B, mma-swizzled
DEVBUF int8_t g_w2q [9 * 8 * 64 * 4];            // conv2 B, dp4a [tap][cg][oc][4]
DEVBUF int8_t g_wl1q[4096 * 1600];               // row-major [n][k]
DEVBUF int8_t g_wl2q[10 * 4096];                 // row-major [n][k]
DEVBUF int8_t g_a1  [1024 * 13 * 13 * 32];       // conv1 out NHWC codes
DEVBUF int8_t g_a2  [1024 * 1600];               // conv2 out NCHW-flat codes
DEVBUF int8_t g_a3  [1024 * 4096];               // fc1 out codes [0,15]
DEVBUF int8_t g_lut1[1009];                      // conv1 acc -> code (+504)
DEVBUF int8_t g_lut2[32257];                     // conv2 acc -> code (+16128)
DEVBUF int8_t g_lut3[179201];                    // fc1  acc -> code (+89600)

// ---------------------------------------------------------------------------
__global__ void __launch_bounds__(256) k_absmax_all(
        const float* __restrict__ w1, const float* __restrict__ w2,
        const float* __restrict__ wl1, const float* __restrict__ wl2) {
    int b = blockIdx.x, tid = threadIdx.x;
    float m = 0.f;
    int slot;
    if (b < 2048) {                               // wl1
        slot = 2;
        const float4* p = (const float4*)wl1;
        for (int i = b * 256 + tid; i < 1638400; i += 2048 * 256) {
            float4 v = p[i];
            m = fmaxf(fmaxf(fabsf(v.x), fabsf(v.y)),
                      fmaxf(fabsf(v.z), fabsf(v.w)));
        }
    } else if (b < 2088) {                        // wl2
        slot = 3;
        float4 v = ((const float4*)wl2)[(b - 2048) * 256 + tid];
        m = fmaxf(fmaxf(fabsf(v.x), fabsf(v.y)), fmaxf(fabsf(v.z), fabsf(v.w)));
    } else if (b < 2106) {                        // w2
        slot = 1;
        float4 v = ((const float4*)w2)[(b - 2088) * 256 + tid];
        m = fmaxf(fmaxf(fabsf(v.x), fabsf(v.y)), fmaxf(fabsf(v.z), fabsf(v.w)));
    } else {                                      // w1
        slot = 0;
        if (tid < 72) {
            float4 v = ((const float4*)w1)[tid];
            m = fmaxf(fmaxf(fabsf(v.x), fabsf(v.y)),
                      fmaxf(fabsf(v.z), fabsf(v.w)));
        }
    }
#pragma unroll
    for (int o = 16; o > 0; o >>= 1)
        m = fmaxf(m, __shfl_xor_sync(0xffffffffu, m, o));
    if ((tid & 31) == 0)
        atomicMax(&g_absmax[slot], __float_as_uint(m));
}

__device__ __forceinline__ int8_t qw7(float x, float s) {
    float t = rintf(__fdiv_rn(x, s));
    return (int8_t)fminf(fmaxf(t, -7.f), 7.f);
}

// Weight quant + both w2 layouts + LUT build, one kernel.
__global__ void __launch_bounds__(256) k_quant_all(
        const float* __restrict__ w1, const float* __restrict__ w2,
        const float* __restrict__ wl1, const float* __restrict__ wl2,
        const float* __restrict__ ps_in, const float* __restrict__ ps_a1,
        const float* __restrict__ ps_a2, const float* __restrict__ ps_a3) {
    int b = blockIdx.x, tid = threadIdx.x;
    if (b < 6400) {                               // wl1 char4
        float s = __fdiv_rn(__uint_as_float(g_absmax[2]), 7.0f);
        int i = b * 256 + tid;
        float4 v = ((const float4*)wl1)[i];
        char4 o;
        o.x = qw7(v.x, s); o.y = qw7(v.y, s);
        o.z = qw7(v.z, s); o.w = qw7(v.w, s);
        ((char4*)g_wl1q)[i] = o;
    } else if (b < 6440) {                        // wl2 char4
        float s = __fdiv_rn(__uint_as_float(g_absmax[3]), 7.0f);
        int i = (b - 6400) * 256 + tid;
        float4 v = ((const float4*)wl2)[i];
        char4 o;
        o.x = qw7(v.x, s); o.y = qw7(v.y, s);
        o.z = qw7(v.z, s); o.w = qw7(v.w, s);
        ((char4*)g_wl2q)[i] = o;
    } else if (b < 6512) {                        // w2 -> both layouts
        float s = __fdiv_rn(__uint_as_float(g_absmax[1]), 7.0f);
        int i = (b - 6440) * 256 + tid;           // < 18432
        int o = i / 288, rem = i % 288, ci = rem / 9, tap = rem % 9;
        int8_t code = qw7(w2[i], s);
        int k = tap * 32 + ci;
        int p = k >> 4;
        g_w2m[o * 384 + (((p ^ (o & 7)) << 4) | (k & 15))] = code;
        g_w2q[((tap * 8 + (ci >> 2)) * 64 + o) * 4 + (ci & 3)] = code;
    } else if (b == 6512) {                       // w1
        float s = __fdiv_rn(__uint_as_float(g_absmax[0]), 7.0f);
        for (int i = tid; i < 288; i += 256) g_w1q[i] = qw7(w1[i], s);
    } else {                                      // LUT build
        int i = (b - 6513) * 256 + tid;
        float s_in = ps_in[0];
        float sw1 = __fdiv_rn(__uint_as_float(g_absmax[0]), 7.0f);
        float sw2 = __fdiv_rn(__uint_as_float(g_absmax[1]), 7.0f);
        float sw3 = __fdiv_rn(__uint_as_float(g_absmax[2]), 7.0f);
        if (i < 1009) {
            float s_a1 = ps_a1[0];
            float v = (float)(i - 504) * (s_in * sw1);
            float t = rintf(__fdiv_rn(v, s_a1));
            t = fminf(fmaxf(t, 0.f), 15.f);
            float t2 = rintf(__fdiv_rn(t * s_a1, s_in));
            g_lut1[i] = (int8_t)fminf(fmaxf(t2, -8.f), 7.f);
        }
        if (i < 32257) {
            float s_a2 = ps_a2[0];
            float v = (float)(i - 16128) * (s_in * sw2);
            float t = rintf(__fdiv_rn(v, s_a2));
            t = fminf(fmaxf(t, 0.f), 15.f);
            float t2 = rintf(__fdiv_rn(t * s_a2, s_in));
            g_lut2[i] = (int8_t)fminf(fmaxf(t2, -8.f), 7.f);
        }
        if (i < 179201) {
            float s_a3 = ps_a3[0];
            float v = (float)(i - 89600) * (s_in * sw3);
            float t = rintf(__fdiv_rn(v, s_a3));
            g_lut3[i] = (int8_t)fminf(fmaxf(t, 0.f), 15.f);
        }
    }
}

// ---------------------------------------------------------------------------
// conv1: quantize x -> 3x3 conv via dp4a -> integer pool-max -> LUT.
__global__ void __launch_bounds__(256) k_conv1(const float* __restrict__ x,
                                               const float* __restrict__ ps_in) {
    __shared__ __align__(4) int8_t sx[28 * 32];
    __shared__ int swa[32][3], swb[32][3];
    __shared__ int8_t slut[1009];
    int b = blockIdx.x, tid = threadIdx.x;
    float s_in = ps_in[0];
    const float* xb = x + b * 784;
    for (int i = tid; i < 784; i += 256) {
        float t = rintf(__fdiv_rn(xb[i], s_in));
        t = fminf(fmaxf(t, -8.f), 7.f);
        sx[(i / 28) * 32 + (i % 28)] = (int8_t)t;
    }
    if (tid < 96) {
        int c = tid / 3, ky = tid % 3;
        int w0 = (int)g_w1q[c * 9 + ky * 3] & 0xff;
        int w1 = (int)g_w1q[c * 9 + ky * 3 + 1] & 0xff;
        int w2 = (int)g_w1q[c * 9 + ky * 3 + 2] & 0xff;
        swa[c][ky] = w0 | (w1 << 8) | (w2 << 16);
        swb[c][ky] = (w0 << 8) | (w1 << 16) | (w2 << 24);
    }
    for (int i = tid; i < 1009; i += 256) slut[i] = g_lut1[i];
    __syncthreads();

    int ch = tid & 31, wq = tid >> 5;
    int wA0 = swa[ch][0], wA1 = swa[ch][1], wA2 = swa[ch][2];
    int wB0 = swb[ch][0], wB1 = swb[ch][1], wB2 = swb[ch][2];
    const int* sxw = (const int*)sx;

    for (int it = 0; it < 22; it++) {
        int win = wq + it * 8;
        if (win >= 169) break;
        int ph = win / 13, pw = win % 13;
        int bytec = 2 * pw, widx = bytec >> 2, sh = bytec & 3;
        int r0 = 2 * ph;
        int rows[4];
#pragma unroll
        for (int r = 0; r < 4; r++) {
            int u = sxw[(r0 + r) * 8 + widx];
            int v = sxw[(r0 + r) * 8 + widx + 1];
            rows[r] = sh ? __byte_perm(u, v, 0x5432) : u;
        }
        int a00 = __dp4a(rows[0], wA0, __dp4a(rows[1], wA1, __dp4a(rows[2], wA2, 0)));
        int a01 = __dp4a(rows[0], wB0, __dp4a(rows[1], wB1, __dp4a(rows[2], wB2, 0)));
        int a10 = __dp4a(rows[1], wA0, __dp4a(rows[2], wA1, __dp4a(rows[3], wA2, 0)));
        int a11 = __dp4a(rows[1], wB0, __dp4a(rows[2], wB1, __dp4a(rows[3], wB2, 0)));
        int amax = max(max(a00, a01), max(a10, a11));
        g_a1[(b * 169 + win) * 32 + ch] = slut[amax + 504];
    }
}

// ---------------------------------------------------------------------------
__device__ __forceinline__ void ldm_x4(uint32_t addr, uint32_t* r) {
    asm volatile("ldmatrix.sync.aligned.m8n8.x4.shared.b16 {%0,%1,%2,%3}, [%4];"
                 : "=r"(r[0]), "=r"(r[1]), "=r"(r[2]), "=r"(r[3]) : "r"(addr));
}
__device__ __forceinline__ void mma_s8(int* c, const uint32_t* a,
                                       uint32_t b0, uint32_t b1) {
    asm volatile(
        "mma.sync.aligned.m16n8k32.row.col.s32.s8.s8.s32 "
        "{%0,%1,%2,%3}, {%4,%5,%6,%7}, {%8,%9}, {%0,%1,%2,%3};"
        : "+r"(c[0]), "+r"(c[1]), "+r"(c[2]), "+r"(c[3])
        : "r"(a[0]), "r"(a[1]), "r"(a[2]), "r"(a[3]), "r"(b0), "r"(b1));
}

// ---------------------------------------------------------------------------
// conv2 hybrid: even images -> mma path (tensor pipe), odd -> dp4a path (alu
// pipe). Both pipes stay busy concurrently on each SM.
__device__ void conv2_mma(int b, int tid, int8_t* dyn2) {
    int8_t* Asm = dyn2;                // 112*384 = 43008
    int8_t* Bsm = dyn2 + 43008;        // 64*384  = 24576
    {
        const int4* src = (const int4*)g_w2m;
        int4* dst = (int4*)Bsm;
#pragma unroll
        for (int i = 0; i < 6; i++) dst[tid + 256 * i] = src[tid + 256 * i];
    }
    {
        const int8_t* img = g_a1 + b * 5408;
        for (int idx = tid; idx < 1800; idx += 256) {
            int r = idx / 18, p = idx - r * 18;
            int win = r >> 2, dp = r & 3;
            int ph = win / 5, pw = win - ph * 5;
            int tap = p >> 1, ky = tap / 3, kx = tap - ky * 3;
            int oy = 2 * ph + (dp >> 1) + ky, ox = 2 * pw + (dp & 1) + kx;
            int4 v = *(const int4*)(img + (oy * 13 + ox) * 32 + (p & 1) * 16);
            *(int4*)(Asm + r * 384 + (((p ^ (r & 7)) << 4))) = v;
        }
    }
    __syncthreads();

    int lane = tid & 31, wid = tid >> 5;
    if (wid >= 7) return;
    int mt = wid;
    int rl = lane & 15, phh = lane >> 4;
    uint32_t smA = (uint32_t)__cvta_generic_to_shared(Asm);
    uint32_t smB = (uint32_t)__cvta_generic_to_shared(Bsm);
    int ra = mt * 16 + rl;
    uint32_t aBase = smA + ra * 384, aXor = (uint32_t)((ra & 7) << 4);
    uint32_t bBase[4], bXor[4];
#pragma unroll
    for (int bt = 0; bt < 4; bt++) {
        int rb = bt * 16 + rl;
        bBase[bt] = smB + rb * 384;
        bXor[bt] = (uint32_t)((rb & 7) << 4);
    }

    int acc[8][4];
#pragma unroll
    for (int i = 0; i < 8; i++)
#pragma unroll
        for (int j = 0; j < 4; j++) acc[i][j] = 0;

#pragma unroll
    for (int s = 0; s < 9; s++) {
        uint32_t pb = (uint32_t)((2 * s + phh) << 4);
        uint32_t af[4];
        ldm_x4(aBase + (pb ^ aXor), af);
        uint32_t bf[4][4];
#pragma unroll
        for (int bt = 0; bt < 4; bt++) ldm_x4(bBase[bt] + (pb ^ bXor[bt]), bf[bt]);
#pragma unroll
        for (int nt = 0; nt < 8; nt++)
            mma_s8(acc[nt], af, bf[nt >> 1][nt & 1], bf[nt >> 1][(nt & 1) + 2]);
    }

    int t4 = lane & 3;
    int winA = mt * 4 + (lane >> 4);
    int winB = winA + 2;
    bool st = ((lane >> 2) & 3) == 0;
    int8_t* dst = g_a2 + b * 1600;
#pragma unroll
    for (int nt = 0; nt < 8; nt++) {
        int m0 = acc[nt][0], m1 = acc[nt][1], m2 = acc[nt][2], m3 = acc[nt][3];
        m0 = max(m0, __shfl_xor_sync(0xffffffffu, m0, 4));
        m0 = max(m0, __shfl_xor_sync(0xffffffffu, m0, 8));
        m1 = max(m1, __shfl_xor_sync(0xffffffffu, m1, 4));
        m1 = max(m1, __shfl_xor_sync(0xffffffffu, m1, 8));
        m2 = max(m2, __shfl_xor_sync(0xffffffffu, m2, 4));
        m2 = max(m2, __shfl_xor_sync(0xffffffffu, m2, 8));
        m3 = max(m3, __shfl_xor_sync(0xffffffffu, m3, 4));
        m3 = max(m3, __shfl_xor_sync(0xffffffffu, m3, 8));
        if (st) {
            int col = nt * 8 + t4 * 2;
            if (winA < 25) {
                dst[col * 25 + winA]       = g_lut2[m0 + 16128];
                dst[(col + 1) * 25 + winA] = g_lut2[m1 + 16128];
            }
            if (winB < 25) {
                dst[col * 25 + winB]       = g_lut2[m2 + 16128];
                dst[(col + 1) * 25 + winB] = g_lut2[m3 + 16128];
            }
        }
    }
}

__device__ void conv2_dp4a(int b, int tid, int8_t* dyn2) {
    int8_t* sa  = dyn2;                // 5408
    int8_t* swq = dyn2 + 5408;         // 18432 (5408 = 338*16, aligned)
    {
        const int4* src = (const int4*)(g_a1 + b * 5408);
        int4* dst = (int4*)sa;
        for (int i = tid; i < 338; i += 256) dst[i] = src[i];
        const int4* ws = (const int4*)g_w2q;
        int4* wd = (int4*)swq;
        for (int i = tid; i < 1152; i += 256) wd[i] = ws[i];
    }
    __syncthreads();
    if (tid >= 200) return;

    int win = tid >> 3, tn = tid & 7;
    int ph = win / 5, pw = win % 5;
    const int* aw = (const int*)sa;
    const int* ww = (const int*)swq;

    int acc[4][8];
#pragma unroll
    for (int i = 0; i < 4; i++)
#pragma unroll
        for (int j = 0; j < 8; j++) acc[i][j] = 0;

#pragma unroll
    for (int ky = 0; ky < 3; ky++) {
#pragma unroll
        for (int kx = 0; kx < 3; kx++) {
            int base[4];
#pragma unroll
            for (int i = 0; i < 4; i++) {
                int dy = i >> 1, dx = i & 1;
                base[i] = ((2 * ph + dy + ky) * 13 + (2 * pw + dx + kx)) * 8;
            }
            int k9 = ky * 3 + kx;
#pragma unroll
            for (int cg = 0; cg < 8; cg++) {
                int av[4];
#pragma unroll
                for (int i = 0; i < 4; i++) av[i] = aw[base[i] + cg];
#pragma unroll
                for (int j = 0; j < 8; j++) {
                    int wv = ww[(k9 * 8 + cg) * 64 + tn * 8 + j];
#pragma unroll
                    for (int i = 0; i < 4; i++)
                        acc[i][j] = __dp4a(av[i], wv, acc[i][j]);
                }
            }
        }
    }
#pragma unroll
    for (int j = 0; j < 8; j++) {
        int qm = max(max(acc[0][j], acc[1][j]), max(acc[2][j], acc[3][j]));
        g_a2[b * 1600 + (tn * 8 + j) * 25 + ph * 5 + pw] = g_lut2[qm + 16128];
    }
}

__global__ void __launch_bounds__(256, 3) k_conv2() {
    extern __shared__ __align__(16) int8_t dyn2[];
    int b = blockIdx.x, tid = threadIdx.x;
    if (b & 1) conv2_dp4a(b, tid, dyn2);
    else       conv2_mma(b, tid, dyn2);
}

// ---------------------------------------------------------------------------
// FC1 hybrid: n-cols [0,2560) via mma (20 blocks of 128), [2560,4096) via
// dp4a (24 blocks of 64). Interleaved in blockIdx order for per-SM pipe mix.
#define CPASYNC16(dst, src) \
    asm volatile("cp.async.cg.shared.global [%0], [%1], 16;" \
                 :: "r"(dst), "l"(src) : "memory")
#define CP_COMMIT() asm volatile("cp.async.commit_group;" ::: "memory")

__shared__ __align__(16) int8_t fc1_sA[3][8192];   // 24KB (mma) / reused dp4a
__shared__ __align__(16) int8_t fc1_sB[3][8192];   // 24KB

__device__ void fc1_mma(int nb, int tid) {
    int8_t (*As)[8192] = fc1_sA;
    int8_t (*Bs)[8192] = fc1_sB;
    int lane = tid & 31, wid = tid >> 5;
    int wm = wid >> 2, wn = wid & 3;
    int m0 = blockIdx.y * 128, n0 = nb * 128;

    int srow = tid >> 2, sp = tid & 3;
    int spp = sp ^ ((srow >> 1) & 3);
    const int8_t* agp = g_a2 + (m0 + srow) * 1600 + sp * 16;
    const int8_t* bgp = g_wl1q + (n0 + srow) * 1600 + sp * 16;
    uint32_t soff = (uint32_t)((srow * 4 + spp) * 16);

    uint32_t sbA = (uint32_t)__cvta_generic_to_shared(As);
    uint32_t sbB = (uint32_t)__cvta_generic_to_shared(Bs);

    int acc[4][4][4];
#pragma unroll
    for (int i = 0; i < 4; i++)
#pragma unroll
        for (int j = 0; j < 4; j++)
#pragma unroll
            for (int k = 0; k < 4; k++) acc[i][j][k] = 0;

    int rl = lane & 15, ph = lane >> 4;
    uint32_t a_addr[4], b_addr[2];
#pragma unroll
    for (int mt = 0; mt < 4; mt++) {
        int r = wm * 64 + mt * 16 + rl;
        int pp = ph ^ ((r >> 1) & 3);
        a_addr[mt] = sbA + (r * 4 + pp) * 16;
    }
#pragma unroll
    for (int bt = 0; bt < 2; bt++) {
        int n = wn * 32 + bt * 16 + rl;
        int pp = ph ^ ((n >> 1) & 3);
        b_addr[bt] = sbB + (n * 4 + pp) * 16;
    }

    auto issue = [&](int ch, int st) {
        uint32_t o = (uint32_t)(st * 8192) + soff;
        const int8_t* ag = agp + ch * 64;
        const int8_t* bg = bgp + ch * 64;
        CPASYNC16(sbA + o,        ag);
        CPASYNC16(sbA + o + 4096, ag + 64 * 1600);
        CPASYNC16(sbB + o,        bg);
        CPASYNC16(sbB + o + 4096, bg + 64 * 1600);
        CP_COMMIT();
    };
    issue(0, 0);
    issue(1, 1);

    for (int chk = 0; chk < 25; chk++) {
        if (chk < 24) asm volatile("cp.async.wait_group 1;" ::: "memory");
        else          asm volatile("cp.async.wait_group 0;" ::: "memory");
        __syncthreads();
        if (chk + 2 < 25) issue(chk + 2, (chk + 2) % 3);
        uint32_t stoff = (uint32_t)((chk % 3) * 8192);
#pragma unroll
        for (int ks = 0; ks < 2; ks++) {
            uint32_t kx = ks ? 32u : 0u;
            uint32_t af[4][4], bf[2][4];
#pragma unroll
            for (int mt = 0; mt < 4; mt++) ldm_x4((a_addr[mt] ^ kx) + stoff, af[mt]);
#pragma unroll
            for (int bt = 0; bt < 2; bt++) ldm_x4((b_addr[bt] ^ kx) + stoff, bf[bt]);
#pragma unroll
            for (int mt = 0; mt < 4; mt++)
#pragma unroll
                for (int nt = 0; nt < 4; nt++)
                    mma_s8(acc[mt][nt], af[mt],
                           bf[nt >> 1][nt & 1], bf[nt >> 1][(nt & 1) + 2]);
        }
    }

    int g = lane >> 2, t4 = lane & 3;
#pragma unroll
    for (int mt = 0; mt < 4; mt++) {
#pragma unroll
        for (int nt = 0; nt < 4; nt++) {
            int mrow = m0 + wm * 64 + mt * 16 + g;
            int ncol = n0 + wn * 32 + nt * 8 + t4 * 2;
#pragma unroll
            for (int h = 0; h < 2; h++) {
                char2 o;
                o.x = g_lut3[acc[mt][nt][2 * h] + 89600];
                o.y = g_lut3[acc[mt][nt][2 * h + 1] + 89600];
                *(char2*)(g_a3 + (mrow + 8 * h) * 4096 + ncol) = o;
            }
        }
    }
}

// dp4a GEMM path (round-3 proven): BM=128 BN=64, thread tile 8x4, LUT epi.
__device__ void fc1_dp4a(int nb, int tid) {
    int (*As)[128] = (int(*)[128])fc1_sA;          // [16][128] = 8KB
    int (*Bs)[64]  = (int(*)[64])fc1_sB;           // [16][64]  = 4KB
    int tx = tid & 15, ty = tid >> 4;
    int m0 = blockIdx.y * 128, n0 = 2560 + nb * 64;
    const int8_t* Ag = g_a2 + m0 * 1600;
    const int8_t* Bg = g_wl1q + n0 * 1600;

    int acc[8][4];
#pragma unroll
    for (int i = 0; i < 8; i++)
#pragma unroll
        for (int j = 0; j < 4; j++) acc[i][j] = 0;

    for (int ch = 0; ch < 25; ch++) {
        for (int i = tid; i < 512; i += 256) {
            int r = i >> 2, wg = i & 3;
            int4 v = *((const int4*)(Ag + r * 1600 + ch * 64) + wg);
            As[wg * 4 + 0][r] = v.x;
            As[wg * 4 + 1][r] = v.y;
            As[wg * 4 + 2][r] = v.z;
            As[wg * 4 + 3][r] = v.w;
        }
        {
            int r = tid >> 2, wg = tid & 3;
            int4 v = *((const int4*)(Bg + r * 1600 + ch * 64) + wg);
            Bs[wg * 4 + 0][r] = v.x;
            Bs[wg * 4 + 1][r] = v.y;
            Bs[wg * 4 + 2][r] = v.z;
            Bs[wg * 4 + 3][r] = v.w;
        }
        __syncthreads();
#pragma unroll 4
        for (int kw = 0; kw < 16; kw++) {
            const int4* ap = (const int4*)(&As[kw][ty * 8]);
            int4 a0 = ap[0], a1 = ap[1];
            int a_[8] = {a0.x, a0.y, a0.z, a0.w, a1.x, a1.y, a1.z, a1.w};
            int b_[4];
#pragma unroll
            for (int j = 0; j < 4; j++) b_[j] = Bs[kw][tx + 16 * j];
#pragma unroll
            for (int i = 0; i < 8; i++)
#pragma unroll
                for (int j = 0; j < 4; j++)
                    acc[i][j] = __dp4a(a_[i], b_[j], acc[i][j]);
        }
        __syncthreads();
    }

#pragma unroll
    for (int i = 0; i < 8; i++) {
        int m = m0 + ty * 8 + i;
#pragma unroll
        for (int j = 0; j < 4; j++) {
            int n = n0 + tx + 16 * j;
            g_a3[m * 4096 + n] = g_lut3[acc[i][j] + 89600];
        }
    }
}

__global__ void __launch_bounds__(256, 2) k_fc1() {
    int bx = blockIdx.x, tid = threadIdx.x;
    int r = bx % 11, q = bx / 11;                  // q in 0..3 (44 blocks/row)
    if (r < 5) fc1_mma(q * 5 + r, tid);            // 20 mma n-blocks
    else       fc1_dp4a(q * 6 + (r - 5), tid);     // 24 dp4a n-blocks
}

// ---------------------------------------------------------------------------
// FC2: [1024,4096] x [10,4096]^T -> f32 out. Two images per block.
__global__ void __launch_bounds__(256) k_fc2(float* __restrict__ out,
                                             const float* __restrict__ ps_a3) {
    __shared__ int red[8][10];
    int tid = threadIdx.x;
    int half = tid >> 7, t = tid & 127;
    int b = blockIdx.x * 2 + half;
    const int* aw = (const int*)g_a3 + b * 1024;
    const int* wp = (const int*)g_wl2q;
    int acc[10];
#pragma unroll
    for (int n = 0; n < 10; n++) acc[n] = 0;
    for (int k = t; k < 1024; k += 128) {
        int a = aw[k];
#pragma unroll
        for (int n = 0; n < 10; n++) acc[n] = __dp4a(a, wp[n * 1024 + k], acc[n]);
    }
#pragma unroll
    for (int n = 0; n < 10; n++)
#pragma unroll
        for (int o = 16; o > 0; o >>= 1)
            acc[n] += __shfl_xor_sync(0xffffffffu, acc[n], o);
    if ((tid & 31) == 0) {
        int w = tid >> 5;
#pragma unroll
        for (int n = 0; n < 10; n++) red[w][n] = acc[n];
    }
    __syncthreads();
    if (t < 10) {
        int w0 = half * 4;
        int s = red[w0][t] + red[w0 + 1][t] + red[w0 + 2][t] + red[w0 + 3][t];
        float s_a3 = ps_a3[0];
        float s_w = __fdiv_rn(__uint_as_float(g_absmax[3]), 7.0f);
        out[b * 10 + t] = (float)s * (s_a3 * s_w);
    }
}

// ---------------------------------------------------------------------------
extern "C" void kernel_launch(void* const* d_in, const int* in_sizes, int n_in,
                              void* d_out, int out_size) {
    const float* x    = (const float*)d_in[0];
    const float* w1   = (const float*)d_in[1];
    const float* w2   = (const float*)d_in[2];
    const float* wl1  = (const float*)d_in[3];
    const float* wl2  = (const float*)d_in[4];
    const float* s_in = (const float*)d_in[5];
    const float* s_a1 = (const float*)d_in[6];
    const float* s_a2 = (const float*)d_in[7];
    const float* s_a3 = (const float*)d_in[8];
    float* out = (float*)d_out;
    (void)in_sizes; (void)n_in; (void)out_size;

    cudaFuncSetAttribute(k_conv2, cudaFuncAttributeMaxDynamicSharedMemorySize,
                         43008 + 24576);

    k_absmax_all<<<2107, 256>>>(w1, w2, wl1, wl2);
    k_quant_all<<<7214, 256>>>(w1, w2, wl1, wl2, s_in, s_a1, s_a2, s_a3);
    k_conv1<<<1024, 256>>>(x, s_in);
    k_conv2<<<1024, 256, 43008 + 24576>>>();
    k_fc1<<<dim3(44, 8), 256>>>();
    k_fc2<<<512, 256>>>(out, s_a3);
}

// round 10
// speedup vs baseline: 1.1108x; 1.1108x over previous
#include <cuda_runtime.h>
#include <cstdint>

// ---------------------------------------------------------------------------
// Quantized LeNet, B=1024. conv1 dp4a, conv2 + FC1 int8 mma.sync (the tensor
// path available at plain sm_103 PTX target). Pool-max commutes with monotone
// quantization -> integer max first; quant chains precomputed into exact LUTs.
// conv2: 2 images/CTA, cp.async double-buffered im2col (stage i+1 under
// compute of i), B tile amortized. Lesson from R9: dp4a and ldmatrix contend
// on the LDS crossbar -> no pipe-splitting; pure mma for the heavy kernels.
// ---------------------------------------------------------------------------

#define DEVBUF __device__ __align__(16)

__device__ unsigned g_absmax[4];                 // zero-init; atomicMax idempotent
DEVBUF int8_t g_w1q [32 * 9];                    // [oc][tap]
DEVBUF int8_t g_w2m [64 * 384];                  // conv2 B, mma-swizzled
DEVBUF int8_t g_wl1q[4096 * 1600];               // row-major [n][k]
DEVBUF int8_t g_wl2q[10 * 4096];                 // row-major [n][k]
DEVBUF int8_t g_a1  [1024 * 13 * 13 * 32];       // conv1 out NHWC codes
DEVBUF int8_t g_a2  [1024 * 1600];               // conv2 out NCHW-flat codes
DEVBUF int8_t g_a3  [1024 * 4096];               // fc1 out codes [0,15]
DEVBUF int8_t g_lut1[1009];                      // conv1 acc -> code (+504)
DEVBUF int8_t g_lut2[32257];                     // conv2 acc -> code (+16128)
DEVBUF int8_t g_lut3[179201];                    // fc1  acc -> code (+89600)

// ---------------------------------------------------------------------------
// abs-max with block reduction: ONE atomic per block (same-address L2 atomics
// serialize; 16K warp-atomics cost ~14 us in R3's profile).
__global__ void __launch_bounds__(256) k_absmax_all(
        const float* __restrict__ w1, const float* __restrict__ w2,
        const float* __restrict__ wl1, const float* __restrict__ wl2) {
    __shared__ float sred[8];
    int b = blockIdx.x, tid = threadIdx.x;
    float m = 0.f;
    int slot;
    if (b < 1024) {                               // wl1: 1638400 float4
        slot = 2;
        const float4* p = (const float4*)wl1;
        for (int i = b * 256 + tid; i < 1638400; i += 1024 * 256) {
            float4 v = p[i];
            m = fmaxf(m, fmaxf(fmaxf(fabsf(v.x), fabsf(v.y)),
                               fmaxf(fabsf(v.z), fabsf(v.w))));
        }
    } else if (b < 1064) {                        // wl2: 10240 float4
        slot = 3;
        float4 v = ((const float4*)wl2)[(b - 1024) * 256 + tid];
        m = fmaxf(fmaxf(fabsf(v.x), fabsf(v.y)), fmaxf(fabsf(v.z), fabsf(v.w)));
    } else if (b < 1082) {                        // w2: 4608 float4
        slot = 1;
        float4 v = ((const float4*)w2)[(b - 1064) * 256 + tid];
        m = fmaxf(fmaxf(fabsf(v.x), fabsf(v.y)), fmaxf(fabsf(v.z), fabsf(v.w)));
    } else {                                      // w1: 72 float4
        slot = 0;
        if (tid < 72) {
            float4 v = ((const float4*)w1)[tid];
            m = fmaxf(fmaxf(fabsf(v.x), fabsf(v.y)),
                      fmaxf(fabsf(v.z), fabsf(v.w)));
        }
    }
#pragma unroll
    for (int o = 16; o > 0; o >>= 1)
        m = fmaxf(m, __shfl_xor_sync(0xffffffffu, m, o));
    if ((tid & 31) == 0) sred[tid >> 5] = m;
    __syncthreads();
    if (tid == 0) {
        float r = sred[0];
#pragma unroll
        for (int w = 1; w < 8; w++) r = fmaxf(r, sred[w]);
        atomicMax(&g_absmax[slot], __float_as_uint(r));
    }
}

__device__ __forceinline__ int8_t qw7(float x, float s) {
    float t = rintf(__fdiv_rn(x, s));
    return (int8_t)fminf(fmaxf(t, -7.f), 7.f);
}

// Weight quant + w2 mma-relayout + LUT build, one kernel.
__global__ void __launch_bounds__(256) k_quant_all(
        const float* __restrict__ w1, const float* __restrict__ w2,
        const float* __restrict__ wl1, const float* __restrict__ wl2,
        const float* __restrict__ ps_in, const float* __restrict__ ps_a1,
        const float* __restrict__ ps_a2, const float* __restrict__ ps_a3) {
    int b = blockIdx.x, tid = threadIdx.x;
    if (b < 6400) {                               // wl1 char4
        float s = __fdiv_rn(__uint_as_float(g_absmax[2]), 7.0f);
        int i = b * 256 + tid;
        float4 v = ((const float4*)wl1)[i];
        char4 o;
        o.x = qw7(v.x, s); o.y = qw7(v.y, s);
        o.z = qw7(v.z, s); o.w = qw7(v.w, s);
        ((char4*)g_wl1q)[i] = o;
    } else if (b < 6440) {                        // wl2 char4
        float s = __fdiv_rn(__uint_as_float(g_absmax[3]), 7.0f);
        int i = (b - 6400) * 256 + tid;
        float4 v = ((const float4*)wl2)[i];
        char4 o;
        o.x = qw7(v.x, s); o.y = qw7(v.y, s);
        o.z = qw7(v.z, s); o.w = qw7(v.w, s);
        ((char4*)g_wl2q)[i] = o;
    } else if (b < 6512) {                        // w2 -> swizzled mma layout
        float s = __fdiv_rn(__uint_as_float(g_absmax[1]), 7.0f);
        int i = (b - 6440) * 256 + tid;           // < 18432
        int o = i / 288, rem = i % 288, ci = rem / 9, tap = rem % 9;
        int k = tap * 32 + ci;
        int p = k >> 4;
        g_w2m[o * 384 + (((p ^ (o & 7)) << 4) | (k & 15))] = qw7(w2[i], s);
    } else if (b == 6512) {                       // w1
        float s = __fdiv_rn(__uint_as_float(g_absmax[0]), 7.0f);
        for (int i = tid; i < 288; i += 256) g_w1q[i] = qw7(w1[i], s);
    } else {                                      // LUT build
        int i = (b - 6513) * 256 + tid;
        float s_in = ps_in[0];
        float sw1 = __fdiv_rn(__uint_as_float(g_absmax[0]), 7.0f);
        float sw2 = __fdiv_rn(__uint_as_float(g_absmax[1]), 7.0f);
        float sw3 = __fdiv_rn(__uint_as_float(g_absmax[2]), 7.0f);
        if (i < 1009) {
            float s_a1 = ps_a1[0];
            float v = (float)(i - 504) * (s_in * sw1);
            float t = rintf(__fdiv_rn(v, s_a1));
            t = fminf(fmaxf(t, 0.f), 15.f);
            float t2 = rintf(__fdiv_rn(t * s_a1, s_in));
            g_lut1[i] = (int8_t)fminf(fmaxf(t2, -8.f), 7.f);
        }
        if (i < 32257) {
            float s_a2 = ps_a2[0];
            float v = (float)(i - 16128) * (s_in * sw2);
            float t = rintf(__fdiv_rn(v, s_a2));
            t = fminf(fmaxf(t, 0.f), 15.f);
            float t2 = rintf(__fdiv_rn(t * s_a2, s_in));
            g_lut2[i] = (int8_t)fminf(fmaxf(t2, -8.f), 7.f);
        }
        if (i < 179201) {
            float s_a3 = ps_a3[0];
            float v = (float)(i - 89600) * (s_in * sw3);
            float t = rintf(__fdiv_rn(v, s_a3));
            g_lut3[i] = (int8_t)fminf(fmaxf(t, 0.f), 15.f);
        }
    }
}

// ---------------------------------------------------------------------------
// conv1: quantize x -> 3x3 conv via dp4a -> integer pool-max -> LUT.
__global__ void __launch_bounds__(256) k_conv1(const float* __restrict__ x,
                                               const float* __restrict__ ps_in) {
    __shared__ __align__(4) int8_t sx[28 * 32];
    __shared__ int swa[32][3], swb[32][3];
    __shared__ int8_t slut[1009];
    int b = blockIdx.x, tid = threadIdx.x;
    float s_in = ps_in[0];
    const float* xb = x + b * 784;
    for (int i = tid; i < 784; i += 256) {
        float t = rintf(__fdiv_rn(xb[i], s_in));
        t = fminf(fmaxf(t, -8.f), 7.f);
        sx[(i / 28) * 32 + (i % 28)] = (int8_t)t;
    }
    if (tid < 96) {
        int c = tid / 3, ky = tid % 3;
        int w0 = (int)g_w1q[c * 9 + ky * 3] & 0xff;
        int w1 = (int)g_w1q[c * 9 + ky * 3 + 1] & 0xff;
        int w2 = (int)g_w1q[c * 9 + ky * 3 + 2] & 0xff;
        swa[c][ky] = w0 | (w1 << 8) | (w2 << 16);
        swb[c][ky] = (w0 << 8) | (w1 << 16) | (w2 << 24);
    }
    for (int i = tid; i < 1009; i += 256) slut[i] = g_lut1[i];
    __syncthreads();

    int ch = tid & 31, wq = tid >> 5;
    int wA0 = swa[ch][0], wA1 = swa[ch][1], wA2 = swa[ch][2];
    int wB0 = swb[ch][0], wB1 = swb[ch][1], wB2 = swb[ch][2];
    const int* sxw = (const int*)sx;

    for (int it = 0; it < 22; it++) {
        int win = wq + it * 8;
        if (win >= 169) break;
        int ph = win / 13, pw = win % 13;
        int bytec = 2 * pw, widx = bytec >> 2, sh = bytec & 3;
        int r0 = 2 * ph;
        int rows[4];
#pragma unroll
        for (int r = 0; r < 4; r++) {
            int u = sxw[(r0 + r) * 8 + widx];
            int v = sxw[(r0 + r) * 8 + widx + 1];
            rows[r] = sh ? __byte_perm(u, v, 0x5432) : u;
        }
        int a00 = __dp4a(rows[0], wA0, __dp4a(rows[1], wA1, __dp4a(rows[2], wA2, 0)));
        int a01 = __dp4a(rows[0], wB0, __dp4a(rows[1], wB1, __dp4a(rows[2], wB2, 0)));
        int a10 = __dp4a(rows[1], wA0, __dp4a(rows[2], wA1, __dp4a(rows[3], wA2, 0)));
        int a11 = __dp4a(rows[1], wB0, __dp4a(rows[2], wB1, __dp4a(rows[3], wB2, 0)));
        int amax = max(max(a00, a01), max(a10, a11));
        g_a1[(b * 169 + win) * 32 + ch] = slut[amax + 504];
    }
}

// ---------------------------------------------------------------------------
__device__ __forceinline__ void ldm_x4(uint32_t addr, uint32_t* r) {
    asm volatile("ldmatrix.sync.aligned.m8n8.x4.shared.b16 {%0,%1,%2,%3}, [%4];"
                 : "=r"(r[0]), "=r"(r[1]), "=r"(r[2]), "=r"(r[3]) : "r"(addr));
}
__device__ __forceinline__ void mma_s8(int* c, const uint32_t* a,
                                       uint32_t b0, uint32_t b1) {
    asm volatile(
        "mma.sync.aligned.m16n8k32.row.col.s32.s8.s8.s32 "
        "{%0,%1,%2,%3}, {%4,%5,%6,%7}, {%8,%9}, {%0,%1,%2,%3};"
        : "+r"(c[0]), "+r"(c[1]), "+r"(c[2]), "+r"(c[3])
        : "r"(a[0]), "r"(a[1]), "r"(a[2]), "r"(a[3]), "r"(b0), "r"(b1));
}
#define CPASYNC16(dst, src) \
    asm volatile("cp.async.cg.shared.global [%0], [%1], 16;" \
                 :: "r"(dst), "l"(src) : "memory")
#define CP_COMMIT() asm volatile("cp.async.commit_group;" ::: "memory")

// ---------------------------------------------------------------------------
// conv2 via mma: 2 images per CTA. cp.async stages im2col A for image i+1
// while image i computes; B (w2m) staged once. smem: A0@0, A1@43008, B@86016.
__global__ void __launch_bounds__(256, 2) k_conv2() {
    extern __shared__ __align__(16) int8_t dyn2[];
    const uint32_t smem = (uint32_t)__cvta_generic_to_shared(dyn2);
    int b0 = blockIdx.x * 2, tid = threadIdx.x;
    int lane = tid & 31, wid = tid >> 5;

    // stage B via cp.async (1536 16B chunks, 6/thread)
    {
        const int8_t* src = g_w2m + tid * 16;
        uint32_t dst = smem + 86016 + tid * 16;
#pragma unroll
        for (int i = 0; i < 6; i++)
            CPASYNC16(dst + i * 4096, src + i * 4096);
    }
    // im2col chunk addresses (same for both images, different base)
    int aoy[8], adst[8];
    int nseg = 0;
    for (int idx = tid; idx < 1800; idx += 256) {
        int r = idx / 18, p = idx - r * 18;
        int win = r >> 2, dp = r & 3;
        int ph = win / 5, pw = win - ph * 5;
        int tap = p >> 1, ky = tap / 3, kx = tap - ky * 3;
        int oy = 2 * ph + (dp >> 1) + ky, ox = 2 * pw + (dp & 1) + kx;
        aoy[nseg] = (oy * 13 + ox) * 32 + (p & 1) * 16;
        adst[nseg] = r * 384 + ((p ^ (r & 7)) << 4);
        nseg++;
    }
    const int8_t* img0 = g_a1 + (size_t)b0 * 5408;
    for (int i = 0; i < nseg; i++)
        CPASYNC16(smem + adst[i], img0 + aoy[i]);
    CP_COMMIT();                                   // group: B + A0
    const int8_t* img1 = img0 + 5408;
    for (int i = 0; i < nseg; i++)
        CPASYNC16(smem + 43008 + adst[i], img1 + aoy[i]);
    CP_COMMIT();                                   // group: A1

    asm volatile("cp.async.wait_group 1;" ::: "memory");
    __syncthreads();

    // per-warp fragment addresses
    int mt = wid;                                  // warps 0..6 compute
    int rl = lane & 15, phh = lane >> 4;
    uint32_t smB = smem + 86016;
    int ra = mt * 16 + rl;
    uint32_t aRow = (uint32_t)(ra * 384), aXor = (uint32_t)((ra & 7) << 4);
    uint32_t bBase[4], bXor[4];
#pragma unroll
    for (int bt = 0; bt < 4; bt++) {
        int rb = bt * 16 + rl;
        bBase[bt] = smB + rb * 384;
        bXor[bt] = (uint32_t)((rb & 7) << 4);
    }
    int t4 = lane & 3;
    int winA = mt * 4 + (lane >> 4);
    int winB = winA + 2;
    bool st = ((lane >> 2) & 3) == 0;

#pragma unroll
    for (int im = 0; im < 2; im++) {
        if (wid < 7) {
            uint32_t aBase = smem + (uint32_t)(im * 43008) + aRow;
            int acc[8][4];
#pragma unroll
            for (int i = 0; i < 8; i++)
#pragma unroll
                for (int j = 0; j < 4; j++) acc[i][j] = 0;
#pragma unroll
            for (int s = 0; s < 9; s++) {
                uint32_t pb = (uint32_t)((2 * s + phh) << 4);
                uint32_t af[4];
                ldm_x4(aBase + (pb ^ aXor), af);
                uint32_t bf[4][4];
#pragma unroll
                for (int bt = 0; bt < 4; bt++)
                    ldm_x4(bBase[bt] + (pb ^ bXor[bt]), bf[bt]);
#pragma unroll
                for (int nt = 0; nt < 8; nt++)
                    mma_s8(acc[nt], af, bf[nt >> 1][nt & 1],
                           bf[nt >> 1][(nt & 1) + 2]);
            }
            int8_t* dst = g_a2 + (size_t)(b0 + im) * 1600;
#pragma unroll
            for (int nt = 0; nt < 8; nt++) {
                int m0 = acc[nt][0], m1 = acc[nt][1];
                int m2 = acc[nt][2], m3 = acc[nt][3];
                m0 = max(m0, __shfl_xor_sync(0xffffffffu, m0, 4));
                m0 = max(m0, __shfl_xor_sync(0xffffffffu, m0, 8));
                m1 = max(m1, __shfl_xor_sync(0xffffffffu, m1, 4));
                m1 = max(m1, __shfl_xor_sync(0xffffffffu, m1, 8));
                m2 = max(m2, __shfl_xor_sync(0xffffffffu, m2, 4));
                m2 = max(m2, __shfl_xor_sync(0xffffffffu, m2, 8));
                m3 = max(m3, __shfl_xor_sync(0xffffffffu, m3, 4));
                m3 = max(m3, __shfl_xor_sync(0xffffffffu, m3, 8));
                if (st) {
                    int col = nt * 8 + t4 * 2;
                    if (winA < 25) {
                        dst[col * 25 + winA]       = g_lut2[m0 + 16128];
                        dst[(col + 1) * 25 + winA] = g_lut2[m1 + 16128];
                    }
                    if (winB < 25) {
                        dst[col * 25 + winB]       = g_lut2[m2 + 16128];
                        dst[(col + 1) * 25 + winB] = g_lut2[m3 + 16128];
                    }
                }
            }
        }
        if (im == 0) {
            asm volatile("cp.async.wait_group 0;" ::: "memory");
            __syncthreads();
        }
    }
}

// ---------------------------------------------------------------------------
// FC1 via int8 mma m16n8k32, BM=128 BN=128 BK=64, double-buffered smem
// (one barrier per chunk), LUT epilogue.  (R6-proven version.)
__global__ void __launch_bounds__(256, 2) k_fc1() {
    __shared__ __align__(16) int8_t As[2][8192];
    __shared__ __align__(16) int8_t Bs[2][8192];
    int tid = threadIdx.x, lane = tid & 31, wid = tid >> 5;
    int wm = wid >> 2, wn = wid & 3;
    int m0 = blockIdx.y * 128, n0 = blockIdx.x * 128;

    int srow = tid >> 2, sp = tid & 3;
    int spp = sp ^ ((srow >> 1) & 3);
    const int8_t* agp = g_a2 + (m0 + srow) * 1600 + sp * 16;
    const int8_t* bgp = g_wl1q + (n0 + srow) * 1600 + sp * 16;
    int soff = (srow * 4 + spp) * 16;

    uint32_t sm_a = (uint32_t)__cvta_generic_to_shared(As[0]);
    uint32_t sm_b = (uint32_t)__cvta_generic_to_shared(Bs[0]);

    int acc[4][4][4];
#pragma unroll
    for (int i = 0; i < 4; i++)
#pragma unroll
        for (int j = 0; j < 4; j++)
#pragma unroll
            for (int k = 0; k < 4; k++) acc[i][j][k] = 0;

    int rl = lane & 15, ph = lane >> 4;
    uint32_t a_addr[4], b_addr[2];
#pragma unroll
    for (int mt = 0; mt < 4; mt++) {
        int r = wm * 64 + mt * 16 + rl;
        int pp = ph ^ ((r >> 1) & 3);
        a_addr[mt] = sm_a + (r * 4 + pp) * 16;
    }
#pragma unroll
    for (int bt = 0; bt < 2; bt++) {
        int n = wn * 32 + bt * 16 + rl;
        int pp = ph ^ ((n >> 1) & 3);
        b_addr[bt] = sm_b + (n * 4 + pp) * 16;
    }

    int4 ra0 = *(const int4*)agp;
    int4 ra1 = *(const int4*)(agp + 64 * 1600);
    int4 rb0 = *(const int4*)bgp;
    int4 rb1 = *(const int4*)(bgp + 64 * 1600);
    *(int4*)(As[0] + soff) = ra0;
    *(int4*)(As[0] + soff + 4096) = ra1;
    *(int4*)(Bs[0] + soff) = rb0;
    *(int4*)(Bs[0] + soff + 4096) = rb1;
    agp += 64; bgp += 64;
    __syncthreads();

    for (int chk = 0; chk < 25; chk++) {
        if (chk < 24) {
            ra0 = *(const int4*)agp;
            ra1 = *(const int4*)(agp + 64 * 1600);
            rb0 = *(const int4*)bgp;
            rb1 = *(const int4*)(bgp + 64 * 1600);
            agp += 64; bgp += 64;
        }
        uint32_t kbuf = (uint32_t)((chk & 1) * 8192);
#pragma unroll
        for (int ks = 0; ks < 2; ks++) {
            uint32_t kx = ks ? 32u : 0u;           // plane ^2 == byte ^32
            uint32_t af[4][4], bf[2][4];
#pragma unroll
            for (int mt = 0; mt < 4; mt++)
                ldm_x4((a_addr[mt] ^ kx) + kbuf, af[mt]);
#pragma unroll
            for (int bt = 0; bt < 2; bt++)
                ldm_x4((b_addr[bt] ^ kx) + kbuf, bf[bt]);
#pragma unroll
            for (int mt = 0; mt < 4; mt++)
#pragma unroll
                for (int nt = 0; nt < 4; nt++)
                    mma_s8(acc[mt][nt], af[mt],
                           bf[nt >> 1][nt & 1], bf[nt >> 1][(nt & 1) + 2]);
        }
        if (chk < 24) {
            int nb = (chk + 1) & 1;
            *(int4*)(As[nb] + soff) = ra0;
            *(int4*)(As[nb] + soff + 4096) = ra1;
            *(int4*)(Bs[nb] + soff) = rb0;
            *(int4*)(Bs[nb] + soff + 4096) = rb1;
            __syncthreads();
        }
    }

    int g = lane >> 2, t4 = lane & 3;
#pragma unroll
    for (int mt = 0; mt < 4; mt++) {
#pragma unroll
        for (int nt = 0; nt < 4; nt++) {
            int mrow = m0 + wm * 64 + mt * 16 + g;
            int ncol = n0 + wn * 32 + nt * 8 + t4 * 2;
#pragma unroll
            for (int h = 0; h < 2; h++) {
                char2 o;
                o.x = g_lut3[acc[mt][nt][2 * h] + 89600];
                o.y = g_lut3[acc[mt][nt][2 * h + 1] + 89600];
                *(char2*)(g_a3 + (mrow + 8 * h) * 4096 + ncol) = o;
            }
        }
    }
}

// ---------------------------------------------------------------------------
// FC2: [1024,4096] x [10,4096]^T -> f32 out. Two images per block.
__global__ void __launch_bounds__(256) k_fc2(float* __restrict__ out,
                                             const float* __restrict__ ps_a3) {
    __shared__ int red[8][10];
    int tid = threadIdx.x;
    int half = tid >> 7, t = tid & 127;
    int b = blockIdx.x * 2 + half;
    const int* aw = (const int*)g_a3 + b * 1024;
    const int* wp = (const int*)g_wl2q;
    int acc[10];
#pragma unroll
    for (int n = 0; n < 10; n++) acc[n] = 0;
    for (int k = t; k < 1024; k += 128) {
        int a = aw[k];
#pragma unroll
        for (int n = 0; n < 10; n++) acc[n] = __dp4a(a, wp[n * 1024 + k], acc[n]);
    }
#pragma unroll
    for (int n = 0; n < 10; n++)
#pragma unroll
        for (int o = 16; o > 0; o >>= 1)
            acc[n] += __shfl_xor_sync(0xffffffffu, acc[n], o);
    if ((tid & 31) == 0) {
        int w = tid >> 5;
#pragma unroll
        for (int n = 0; n < 10; n++) red[w][n] = acc[n];
    }
    __syncthreads();
    if (t < 10) {
        int w0 = half * 4;
        int s = red[w0][t] + red[w0 + 1][t] + red[w0 + 2][t] + red[w0 + 3][t];
        float s_a3 = ps_a3[0];
        float s_w = __fdiv_rn(__uint_as_float(g_absmax[3]), 7.0f);
        out[b * 10 + t] = (float)s * (s_a3 * s_w);
    }
}

// ---------------------------------------------------------------------------
extern "C" void kernel_launch(void* const* d_in, const int* in_sizes, int n_in,
                              void* d_out, int out_size) {
    const float* x    = (const float*)d_in[0];
    const float* w1   = (const float*)d_in[1];
    const float* w2   = (const float*)d_in[2];
    const float* wl1  = (const float*)d_in[3];
    const float* wl2  = (const float*)d_in[4];
    const float* s_in = (const float*)d_in[5];
    const float* s_a1 = (const float*)d_in[6];
    const float* s_a2 = (const float*)d_in[7];
    const float* s_a3 = (const float*)d_in[8];
    float* out = (float*)d_out;
    (void)in_sizes; (void)n_in; (void)out_size;

    cudaFuncSetAttribute(k_conv2, cudaFuncAttributeMaxDynamicSharedMemorySize,
                         2 * 43008 + 24576);

    k_absmax_all<<<1083, 256>>>(w1, w2, wl1, wl2);
    k_quant_all<<<7214, 256>>>(w1, w2, wl1, wl2, s_in, s_a1, s_a2, s_a3);
    k_conv1<<<1024, 256>>>(x, s_in);
    k_conv2<<<512, 256, 2 * 43008 + 24576>>>();
    k_fc1<<<dim3(4096 / 128, 1024 / 128), 256>>>();
    k_fc2<<<512, 256>>>(out, s_a3);
}

// round 11
// speedup vs baseline: 1.2185x; 1.0970x over previous
#include <cuda_runtime.h>
#include <cstdint>

// ---------------------------------------------------------------------------
// Quantized LeNet, B=1024. conv1 dp4a, conv2 + FC1 int8 mma.sync (the tensor
// path available at plain sm_103 PTX target). Pool-max commutes with monotone
// quantization -> integer max first; quant chains precomputed into exact LUTs.
// Composition of measured-best variants: R8 conv2 (single image, now with
// cp.async staging), R6 fc1 (reg-prefetch double buffer), R10 absmax
// (block-reduced atomics), R8 fc2 (2 images/block).
// ---------------------------------------------------------------------------

#define DEVBUF __device__ __align__(16)

__device__ unsigned g_absmax[4];                 // zero-init; atomicMax idempotent
DEVBUF int8_t g_w1q [32 * 9];                    // [oc][tap]
DEVBUF int8_t g_w2m [64 * 384];                  // conv2 B, mma-swizzled
DEVBUF int8_t g_wl1q[4096 * 1600];               // row-major [n][k]
DEVBUF int8_t g_wl2q[10 * 4096];                 // row-major [n][k]
DEVBUF int8_t g_a1  [1024 * 13 * 13 * 32];       // conv1 out NHWC codes
DEVBUF int8_t g_a2  [1024 * 1600];               // conv2 out NCHW-flat codes
DEVBUF int8_t g_a3  [1024 * 4096];               // fc1 out codes [0,15]
DEVBUF int8_t g_lut1[1009];                      // conv1 acc -> code (+504)
DEVBUF int8_t g_lut2[32257];                     // conv2 acc -> code (+16128)
DEVBUF int8_t g_lut3[179201];                    // fc1  acc -> code (+89600)

// ---------------------------------------------------------------------------
// abs-max with block reduction: ONE atomic per block.
__global__ void __launch_bounds__(256) k_absmax_all(
        const float* __restrict__ w1, const float* __restrict__ w2,
        const float* __restrict__ wl1, const float* __restrict__ wl2) {
    __shared__ float sred[8];
    int b = blockIdx.x, tid = threadIdx.x;
    float m = 0.f;
    int slot;
    if (b < 1024) {                               // wl1: 1638400 float4
        slot = 2;
        const float4* p = (const float4*)wl1;
        for (int i = b * 256 + tid; i < 1638400; i += 1024 * 256) {
            float4 v = p[i];
            m = fmaxf(m, fmaxf(fmaxf(fabsf(v.x), fabsf(v.y)),
                               fmaxf(fabsf(v.z), fabsf(v.w))));
        }
    } else if (b < 1064) {                        // wl2
        slot = 3;
        float4 v = ((const float4*)wl2)[(b - 1024) * 256 + tid];
        m = fmaxf(fmaxf(fabsf(v.x), fabsf(v.y)), fmaxf(fabsf(v.z), fabsf(v.w)));
    } else if (b < 1082) {                        // w2
        slot = 1;
        float4 v = ((const float4*)w2)[(b - 1064) * 256 + tid];
        m = fmaxf(fmaxf(fabsf(v.x), fabsf(v.y)), fmaxf(fabsf(v.z), fabsf(v.w)));
    } else {                                      // w1
        slot = 0;
        if (tid < 72) {
            float4 v = ((const float4*)w1)[tid];
            m = fmaxf(fmaxf(fabsf(v.x), fabsf(v.y)),
                      fmaxf(fabsf(v.z), fabsf(v.w)));
        }
    }
#pragma unroll
    for (int o = 16; o > 0; o >>= 1)
        m = fmaxf(m, __shfl_xor_sync(0xffffffffu, m, o));
    if ((tid & 31) == 0) sred[tid >> 5] = m;
    __syncthreads();
    if (tid == 0) {
        float r = sred[0];
#pragma unroll
        for (int w = 1; w < 8; w++) r = fmaxf(r, sred[w]);
        atomicMax(&g_absmax[slot], __float_as_uint(r));
    }
}

__device__ __forceinline__ int8_t qw7(float x, float s) {
    float t = rintf(__fdiv_rn(x, s));
    return (int8_t)fminf(fmaxf(t, -7.f), 7.f);
}

// Weight quant + w2 mma-relayout + LUT build, one kernel.
__global__ void __launch_bounds__(256) k_quant_all(
        const float* __restrict__ w1, const float* __restrict__ w2,
        const float* __restrict__ wl1, const float* __restrict__ wl2,
        const float* __restrict__ ps_in, const float* __restrict__ ps_a1,
        const float* __restrict__ ps_a2, const float* __restrict__ ps_a3) {
    int b = blockIdx.x, tid = threadIdx.x;
    if (b < 6400) {                               // wl1 char4
        float s = __fdiv_rn(__uint_as_float(g_absmax[2]), 7.0f);
        int i = b * 256 + tid;
        float4 v = ((const float4*)wl1)[i];
        char4 o;
        o.x = qw7(v.x, s); o.y = qw7(v.y, s);
        o.z = qw7(v.z, s); o.w = qw7(v.w, s);
        ((char4*)g_wl1q)[i] = o;
    } else if (b < 6440) {                        // wl2 char4
        float s = __fdiv_rn(__uint_as_float(g_absmax[3]), 7.0f);
        int i = (b - 6400) * 256 + tid;
        float4 v = ((const float4*)wl2)[i];
        char4 o;
        o.x = qw7(v.x, s); o.y = qw7(v.y, s);
        o.z = qw7(v.z, s); o.w = qw7(v.w, s);
        ((char4*)g_wl2q)[i] = o;
    } else if (b < 6512) {                        // w2 -> swizzled mma layout
        float s = __fdiv_rn(__uint_as_float(g_absmax[1]), 7.0f);
        int i = (b - 6440) * 256 + tid;           // < 18432
        int o = i / 288, rem = i % 288, ci = rem / 9, tap = rem % 9;
        int k = tap * 32 + ci;
        int p = k >> 4;
        g_w2m[o * 384 + (((p ^ (o & 7)) << 4) | (k & 15))] = qw7(w2[i], s);
    } else if (b == 6512) {                       // w1
        float s = __fdiv_rn(__uint_as_float(g_absmax[0]), 7.0f);
        for (int i = tid; i < 288; i += 256) g_w1q[i] = qw7(w1[i], s);
    } else {                                      // LUT build
        int i = (b - 6513) * 256 + tid;
        float s_in = ps_in[0];
        float sw1 = __fdiv_rn(__uint_as_float(g_absmax[0]), 7.0f);
        float sw2 = __fdiv_rn(__uint_as_float(g_absmax[1]), 7.0f);
        float sw3 = __fdiv_rn(__uint_as_float(g_absmax[2]), 7.0f);
        if (i < 1009) {
            float s_a1 = ps_a1[0];
            float v = (float)(i - 504) * (s_in * sw1);
            float t = rintf(__fdiv_rn(v, s_a1));
            t = fminf(fmaxf(t, 0.f), 15.f);
            float t2 = rintf(__fdiv_rn(t * s_a1, s_in));
            g_lut1[i] = (int8_t)fminf(fmaxf(t2, -8.f), 7.f);
        }
        if (i < 32257) {
            float s_a2 = ps_a2[0];
            float v = (float)(i - 16128) * (s_in * sw2);
            float t = rintf(__fdiv_rn(v, s_a2));
            t = fminf(fmaxf(t, 0.f), 15.f);
            float t2 = rintf(__fdiv_rn(t * s_a2, s_in));
            g_lut2[i] = (int8_t)fminf(fmaxf(t2, -8.f), 7.f);
        }
        if (i < 179201) {
            float s_a3 = ps_a3[0];
            float v = (float)(i - 89600) * (s_in * sw3);
            float t = rintf(__fdiv_rn(v, s_a3));
            g_lut3[i] = (int8_t)fminf(fmaxf(t, 0.f), 15.f);
        }
    }
}

// ---------------------------------------------------------------------------
// conv1: quantize x -> 3x3 conv via dp4a -> integer pool-max -> LUT.
__global__ void __launch_bounds__(256) k_conv1(const float* __restrict__ x,
                                               const float* __restrict__ ps_in) {
    __shared__ __align__(4) int8_t sx[28 * 32];
    __shared__ int swa[32][3], swb[32][3];
    __shared__ int8_t slut[1009];
    int b = blockIdx.x, tid = threadIdx.x;
    float s_in = ps_in[0];
    const float* xb = x + b * 784;
    for (int i = tid; i < 784; i += 256) {
        float t = rintf(__fdiv_rn(xb[i], s_in));
        t = fminf(fmaxf(t, -8.f), 7.f);
        sx[(i / 28) * 32 + (i % 28)] = (int8_t)t;
    }
    if (tid < 96) {
        int c = tid / 3, ky = tid % 3;
        int w0 = (int)g_w1q[c * 9 + ky * 3] & 0xff;
        int w1 = (int)g_w1q[c * 9 + ky * 3 + 1] & 0xff;
        int w2 = (int)g_w1q[c * 9 + ky * 3 + 2] & 0xff;
        swa[c][ky] = w0 | (w1 << 8) | (w2 << 16);
        swb[c][ky] = (w0 << 8) | (w1 << 16) | (w2 << 24);
    }
    for (int i = tid; i < 1009; i += 256) slut[i] = g_lut1[i];
    __syncthreads();

    int ch = tid & 31, wq = tid >> 5;
    int wA0 = swa[ch][0], wA1 = swa[ch][1], wA2 = swa[ch][2];
    int wB0 = swb[ch][0], wB1 = swb[ch][1], wB2 = swb[ch][2];
    const int* sxw = (const int*)sx;

    for (int it = 0; it < 22; it++) {
        int win = wq + it * 8;
        if (win >= 169) break;
        int ph = win / 13, pw = win % 13;
        int bytec = 2 * pw, widx = bytec >> 2, sh = bytec & 3;
        int r0 = 2 * ph;
        int rows[4];
#pragma unroll
        for (int r = 0; r < 4; r++) {
            int u = sxw[(r0 + r) * 8 + widx];
            int v = sxw[(r0 + r) * 8 + widx + 1];
            rows[r] = sh ? __byte_perm(u, v, 0x5432) : u;
        }
        int a00 = __dp4a(rows[0], wA0, __dp4a(rows[1], wA1, __dp4a(rows[2], wA2, 0)));
        int a01 = __dp4a(rows[0], wB0, __dp4a(rows[1], wB1, __dp4a(rows[2], wB2, 0)));
        int a10 = __dp4a(rows[1], wA0, __dp4a(rows[2], wA1, __dp4a(rows[3], wA2, 0)));
        int a11 = __dp4a(rows[1], wB0, __dp4a(rows[2], wB1, __dp4a(rows[3], wB2, 0)));
        int amax = max(max(a00, a01), max(a10, a11));
        g_a1[(b * 169 + win) * 32 + ch] = slut[amax + 504];
    }
}

// ---------------------------------------------------------------------------
__device__ __forceinline__ void ldm_x4(uint32_t addr, uint32_t* r) {
    asm volatile("ldmatrix.sync.aligned.m8n8.x4.shared.b16 {%0,%1,%2,%3}, [%4];"
                 : "=r"(r[0]), "=r"(r[1]), "=r"(r[2]), "=r"(r[3]) : "r"(addr));
}
__device__ __forceinline__ void mma_s8(int* c, const uint32_t* a,
                                       uint32_t b0, uint32_t b1) {
    asm volatile(
        "mma.sync.aligned.m16n8k32.row.col.s32.s8.s8.s32 "
        "{%0,%1,%2,%3}, {%4,%5,%6,%7}, {%8,%9}, {%0,%1,%2,%3};"
        : "+r"(c[0]), "+r"(c[1]), "+r"(c[2]), "+r"(c[3])
        : "r"(a[0]), "r"(a[1]), "r"(a[2]), "r"(a[3]), "r"(b0), "r"(b1));
}
#define CPASYNC16(dst, src) \
    asm volatile("cp.async.cg.shared.global [%0], [%1], 16;" \
                 :: "r"(dst), "l"(src) : "memory")
#define CP_COMMIT() asm volatile("cp.async.commit_group;" ::: "memory")

// ---------------------------------------------------------------------------
// conv2 via mma: one image per CTA (R8 structure), cp.async staging (no
// register round-trip). A im2col [112 x 288] swizzled, B = g_w2m [64 x 288].
// Pool via shfl-max, then LUT.
__global__ void __launch_bounds__(256, 3) k_conv2() {
    extern __shared__ __align__(16) int8_t dyn2[];
    const uint32_t smem = (uint32_t)__cvta_generic_to_shared(dyn2);
    int b = blockIdx.x, tid = threadIdx.x;
    int lane = tid & 31, wid = tid >> 5;

    // stage B via cp.async: 1536 16B segs, 6 per thread
    {
        const int8_t* src = g_w2m + tid * 16;
        uint32_t dst = smem + 43008 + tid * 16;
#pragma unroll
        for (int i = 0; i < 6; i++)
            CPASYNC16(dst + i * 4096, src + i * 4096);
    }
    // stage A im2col via cp.async: 1800 16B segs
    {
        const int8_t* img = g_a1 + (size_t)b * 5408;
        for (int idx = tid; idx < 1800; idx += 256) {
            int r = idx / 18, p = idx - r * 18;
            int win = r >> 2, dp = r & 3;
            int ph = win / 5, pw = win - ph * 5;
            int tap = p >> 1, ky = tap / 3, kx = tap - ky * 3;
            int oy = 2 * ph + (dp >> 1) + ky, ox = 2 * pw + (dp & 1) + kx;
            CPASYNC16(smem + r * 384 + ((p ^ (r & 7)) << 4),
                      img + (oy * 13 + ox) * 32 + (p & 1) * 16);
        }
    }
    CP_COMMIT();
    asm volatile("cp.async.wait_group 0;" ::: "memory");
    __syncthreads();

    if (wid >= 7) return;
    int mt = wid;
    int rl = lane & 15, phh = lane >> 4;
    uint32_t smB = smem + 43008;
    int ra = mt * 16 + rl;
    uint32_t aBase = smem + ra * 384, aXor = (uint32_t)((ra & 7) << 4);
    uint32_t bBase[4], bXor[4];
#pragma unroll
    for (int bt = 0; bt < 4; bt++) {
        int rb = bt * 16 + rl;
        bBase[bt] = smB + rb * 384;
        bXor[bt] = (uint32_t)((rb & 7) << 4);
    }

    int acc[8][4];
#pragma unroll
    for (int i = 0; i < 8; i++)
#pragma unroll
        for (int j = 0; j < 4; j++) acc[i][j] = 0;

#pragma unroll
    for (int s = 0; s < 9; s++) {
        uint32_t pb = (uint32_t)((2 * s + phh) << 4);
        uint32_t af[4];
        ldm_x4(aBase + (pb ^ aXor), af);
        uint32_t bf[4][4];
#pragma unroll
        for (int bt = 0; bt < 4; bt++) ldm_x4(bBase[bt] + (pb ^ bXor[bt]), bf[bt]);
#pragma unroll
        for (int nt = 0; nt < 8; nt++)
            mma_s8(acc[nt], af, bf[nt >> 1][nt & 1], bf[nt >> 1][(nt & 1) + 2]);
    }

    int t4 = lane & 3;
    int winA = mt * 4 + (lane >> 4);
    int winB = winA + 2;
    bool st = ((lane >> 2) & 3) == 0;
    int8_t* dst = g_a2 + (size_t)b * 1600;
#pragma unroll
    for (int nt = 0; nt < 8; nt++) {
        int m0 = acc[nt][0], m1 = acc[nt][1], m2 = acc[nt][2], m3 = acc[nt][3];
        m0 = max(m0, __shfl_xor_sync(0xffffffffu, m0, 4));
        m0 = max(m0, __shfl_xor_sync(0xffffffffu, m0, 8));
        m1 = max(m1, __shfl_xor_sync(0xffffffffu, m1, 4));
        m1 = max(m1, __shfl_xor_sync(0xffffffffu, m1, 8));
        m2 = max(m2, __shfl_xor_sync(0xffffffffu, m2, 4));
        m2 = max(m2, __shfl_xor_sync(0xffffffffu, m2, 8));
        m3 = max(m3, __shfl_xor_sync(0xffffffffu, m3, 4));
        m3 = max(m3, __shfl_xor_sync(0xffffffffu, m3, 8));
        if (st) {
            int col = nt * 8 + t4 * 2;
            if (winA < 25) {
                dst[col * 25 + winA]       = g_lut2[m0 + 16128];
                dst[(col + 1) * 25 + winA] = g_lut2[m1 + 16128];
            }
            if (winB < 25) {
                dst[col * 25 + winB]       = g_lut2[m2 + 16128];
                dst[(col + 1) * 25 + winB] = g_lut2[m3 + 16128];
            }
        }
    }
}

// ---------------------------------------------------------------------------
// FC1 via int8 mma m16n8k32, BM=128 BN=128 BK=64, double-buffered smem
// (one barrier per chunk), LUT epilogue.  (R6-proven, best measured.)
__global__ void __launch_bounds__(256, 2) k_fc1() {
    __shared__ __align__(16) int8_t As[2][8192];
    __shared__ __align__(16) int8_t Bs[2][8192];
    int tid = threadIdx.x, lane = tid & 31, wid = tid >> 5;
    int wm = wid >> 2, wn = wid & 3;
    int m0 = blockIdx.y * 128, n0 = blockIdx.x * 128;

    int srow = tid >> 2, sp = tid & 3;
    int spp = sp ^ ((srow >> 1) & 3);
    const int8_t* agp = g_a2 + (m0 + srow) * 1600 + sp * 16;
    const int8_t* bgp = g_wl1q + (n0 + srow) * 1600 + sp * 16;
    int soff = (srow * 4 + spp) * 16;

    uint32_t sm_a = (uint32_t)__cvta_generic_to_shared(As[0]);
    uint32_t sm_b = (uint32_t)__cvta_generic_to_shared(Bs[0]);

    int acc[4][4][4];
#pragma unroll
    for (int i = 0; i < 4; i++)
#pragma unroll
        for (int j = 0; j < 4; j++)
#pragma unroll
            for (int k = 0; k < 4; k++) acc[i][j][k] = 0;

    int rl = lane & 15, ph = lane >> 4;
    uint32_t a_addr[4], b_addr[2];
#pragma unroll
    for (int mt = 0; mt < 4; mt++) {
        int r = wm * 64 + mt * 16 + rl;
        int pp = ph ^ ((r >> 1) & 3);
        a_addr[mt] = sm_a + (r * 4 + pp) * 16;
    }
#pragma unroll
    for (int bt = 0; bt < 2; bt++) {
        int n = wn * 32 + bt * 16 + rl;
        int pp = ph ^ ((n >> 1) & 3);
        b_addr[bt] = sm_b + (n * 4 + pp) * 16;
    }

    int4 ra0 = *(const int4*)agp;
    int4 ra1 = *(const int4*)(agp + 64 * 1600);
    int4 rb0 = *(const int4*)bgp;
    int4 rb1 = *(const int4*)(bgp + 64 * 1600);
    *(int4*)(As[0] + soff) = ra0;
    *(int4*)(As[0] + soff + 4096) = ra1;
    *(int4*)(Bs[0] + soff) = rb0;
    *(int4*)(Bs[0] + soff + 4096) = rb1;
    agp += 64; bgp += 64;
    __syncthreads();

    for (int chk = 0; chk < 25; chk++) {
        if (chk < 24) {
            ra0 = *(const int4*)agp;
            ra1 = *(const int4*)(agp + 64 * 1600);
            rb0 = *(const int4*)bgp;
            rb1 = *(const int4*)(bgp + 64 * 1600);
            agp += 64; bgp += 64;
        }
        uint32_t kbuf = (uint32_t)((chk & 1) * 8192);
#pragma unroll
        for (int ks = 0; ks < 2; ks++) {
            uint32_t kx = ks ? 32u : 0u;           // plane ^2 == byte ^32
            uint32_t af[4][4], bf[2][4];
#pragma unroll
            for (int mt = 0; mt < 4; mt++)
                ldm_x4((a_addr[mt] ^ kx) + kbuf, af[mt]);
#pragma unroll
            for (int bt = 0; bt < 2; bt++)
                ldm_x4((b_addr[bt] ^ kx) + kbuf, bf[bt]);
#pragma unroll
            for (int mt = 0; mt < 4; mt++)
#pragma unroll
                for (int nt = 0; nt < 4; nt++)
                    mma_s8(acc[mt][nt], af[mt],
                           bf[nt >> 1][nt & 1], bf[nt >> 1][(nt & 1) + 2]);
        }
        if (chk < 24) {
            int nb = (chk + 1) & 1;
            *(int4*)(As[nb] + soff) = ra0;
            *(int4*)(As[nb] + soff + 4096) = ra1;
            *(int4*)(Bs[nb] + soff) = rb0;
            *(int4*)(Bs[nb] + soff + 4096) = rb1;
            __syncthreads();
        }
    }

    int g = lane >> 2, t4 = lane & 3;
#pragma unroll
    for (int mt = 0; mt < 4; mt++) {
#pragma unroll
        for (int nt = 0; nt < 4; nt++) {
            int mrow = m0 + wm * 64 + mt * 16 + g;
            int ncol = n0 + wn * 32 + nt * 8 + t4 * 2;
#pragma unroll
            for (int h = 0; h < 2; h++) {
                char2 o;
                o.x = g_lut3[acc[mt][nt][2 * h] + 89600];
                o.y = g_lut3[acc[mt][nt][2 * h + 1] + 89600];
                *(char2*)(g_a3 + (mrow + 8 * h) * 4096 + ncol) = o;
            }
        }
    }
}

// ---------------------------------------------------------------------------
// FC2: [1024,4096] x [10,4096]^T -> f32 out. Two images per block.
__global__ void __launch_bounds__(256) k_fc2(float* __restrict__ out,
                                             const float* __restrict__ ps_a3) {
    __shared__ int red[8][10];
    int tid = threadIdx.x;
    int half = tid >> 7, t = tid & 127;
    int b = blockIdx.x * 2 + half;
    const int* aw = (const int*)g_a3 + b * 1024;
    const int* wp = (const int*)g_wl2q;
    int acc[10];
#pragma unroll
    for (int n = 0; n < 10; n++) acc[n] = 0;
    for (int k = t; k < 1024; k += 128) {
        int a = aw[k];
#pragma unroll
        for (int n = 0; n < 10; n++) acc[n] = __dp4a(a, wp[n * 1024 + k], acc[n]);
    }
#pragma unroll
    for (int n = 0; n < 10; n++)
#pragma unroll
        for (int o = 16; o > 0; o >>= 1)
            acc[n] += __shfl_xor_sync(0xffffffffu, acc[n], o);
    if ((tid & 31) == 0) {
        int w = tid >> 5;
#pragma unroll
        for (int n = 0; n < 10; n++) red[w][n] = acc[n];
    }
    __syncthreads();
    if (t < 10) {
        int w0 = half * 4;
        int s = red[w0][t] + red[w0 + 1][t] + red[w0 + 2][t] + red[w0 + 3][t];
        float s_a3 = ps_a3[0];
        float s_w = __fdiv_rn(__uint_as_float(g_absmax[3]), 7.0f);
        out[b * 10 + t] = (float)s * (s_a3 * s_w);
    }
}

// ---------------------------------------------------------------------------
extern "C" void kernel_launch(void* const* d_in, const int* in_sizes, int n_in,
                              void* d_out, int out_size) {
    const float* x    = (const float*)d_in[0];
    const float* w1   = (const float*)d_in[1];
    const float* w2   = (const float*)d_in[2];
    const float* wl1  = (const float*)d_in[3];
    const float* wl2  = (const float*)d_in[4];
    const float* s_in = (const float*)d_in[5];
    const float* s_a1 = (const float*)d_in[6];
    const float* s_a2 = (const float*)d_in[7];
    const float* s_a3 = (const float*)d_in[8];
    float* out = (float*)d_out;
    (void)in_sizes; (void)n_in; (void)out_size;

    cudaFuncSetAttribute(k_conv2, cudaFuncAttributeMaxDynamicSharedMemorySize,
                         43008 + 24576);

    k_absmax_all<<<1083, 256>>>(w1, w2, wl1, wl2);
    k_quant_all<<<7214, 256>>>(w1, w2, wl1, wl2, s_in, s_a1, s_a2, s_a3);
    k_conv1<<<1024, 256>>>(x, s_in);
    k_conv2<<<1024, 256, 43008 + 24576>>>();
    k_fc1<<<dim3(4096 / 128, 1024 / 128), 256>>>();
    k_fc2<<<512, 256>>>(out, s_a3);
}

// round 12
// speedup vs baseline: 1.6496x; 1.3538x over previous
#include <cuda_runtime.h>
#include <cuda_fp16.h>
#include <cstdint>

// ---------------------------------------------------------------------------
// Quantized LeNet, B=1024. conv1 dp4a, conv2 int8 mma.sync (proven R11),
// FC1 fp16 mma.sync m16n8k16 (f32 acc) — exact: all operands are small
// integers (fp16-exact), acc < 2^24. Pool-max commutes with monotone quant;
// quant chains precomputed into exact LUTs.
// ---------------------------------------------------------------------------

#define DEVBUF __device__ __align__(16)

__device__ unsigned g_absmax[4];                 // zero-init; atomicMax idempotent
DEVBUF int8_t   g_w1q [32 * 9];                  // [oc][tap]
DEVBUF int8_t   g_w2m [64 * 384];                // conv2 B, mma-swizzled
DEVBUF uint16_t g_wl1h[4096 * 1600];             // wl1 codes as fp16 [n][k]
DEVBUF int8_t   g_wl2q[10 * 4096];               // row-major [n][k]
DEVBUF int8_t   g_a1  [1024 * 13 * 13 * 32];     // conv1 out NHWC codes
DEVBUF uint16_t g_a2h [1024 * 1600];             // conv2 out codes as fp16
DEVBUF int8_t   g_a3  [1024 * 4096];             // fc1 out codes [0,15]
DEVBUF int8_t   g_lut1[1009];                    // conv1 acc -> code (+504)
DEVBUF uint16_t g_lut2h[32257];                  // conv2 acc -> fp16 code (+16128)
DEVBUF int8_t   g_lut3[179201];                  // fc1  acc -> code (+89600)

// ---------------------------------------------------------------------------
// abs-max with block reduction: ONE atomic per block.
__global__ void __launch_bounds__(256) k_absmax_all(
        const float* __restrict__ w1, const float* __restrict__ w2,
        const float* __restrict__ wl1, const float* __restrict__ wl2) {
    __shared__ float sred[8];
    int b = blockIdx.x, tid = threadIdx.x;
    float m = 0.f;
    int slot;
    if (b < 1024) {                               // wl1: 1638400 float4
        slot = 2;
        const float4* p = (const float4*)wl1;
        for (int i = b * 256 + tid; i < 1638400; i += 1024 * 256) {
            float4 v = p[i];
            m = fmaxf(m, fmaxf(fmaxf(fabsf(v.x), fabsf(v.y)),
                               fmaxf(fabsf(v.z), fabsf(v.w))));
        }
    } else if (b < 1064) {                        // wl2
        slot = 3;
        float4 v = ((const float4*)wl2)[(b - 1024) * 256 + tid];
        m = fmaxf(fmaxf(fabsf(v.x), fabsf(v.y)), fmaxf(fabsf(v.z), fabsf(v.w)));
    } else if (b < 1082) {                        // w2
        slot = 1;
        float4 v = ((const float4*)w2)[(b - 1064) * 256 + tid];
        m = fmaxf(fmaxf(fabsf(v.x), fabsf(v.y)), fmaxf(fabsf(v.z), fabsf(v.w)));
    } else {                                      // w1
        slot = 0;
        if (tid < 72) {
            float4 v = ((const float4*)w1)[tid];
            m = fmaxf(fmaxf(fabsf(v.x), fabsf(v.y)),
                      fmaxf(fabsf(v.z), fabsf(v.w)));
        }
    }
#pragma unroll
    for (int o = 16; o > 0; o >>= 1)
        m = fmaxf(m, __shfl_xor_sync(0xffffffffu, m, o));
    if ((tid & 31) == 0) sred[tid >> 5] = m;
    __syncthreads();
    if (tid == 0) {
        float r = sred[0];
#pragma unroll
        for (int w = 1; w < 8; w++) r = fmaxf(r, sred[w]);
        atomicMax(&g_absmax[slot], __float_as_uint(r));
    }
}

__device__ __forceinline__ float qw7f(float x, float s) {
    float t = rintf(__fdiv_rn(x, s));
    return fminf(fmaxf(t, -7.f), 7.f);
}
__device__ __forceinline__ uint16_t f2h(float f) {
    return __half_as_ushort(__float2half_rn(f));  // exact for small ints
}

// Weight quant + w2 mma-relayout + LUT build, one kernel.
__global__ void __launch_bounds__(256) k_quant_all(
        const float* __restrict__ w1, const float* __restrict__ w2,
        const float* __restrict__ wl1, const float* __restrict__ wl2,
        const float* __restrict__ ps_in, const float* __restrict__ ps_a1,
        const float* __restrict__ ps_a2, const float* __restrict__ ps_a3) {
    int b = blockIdx.x, tid = threadIdx.x;
    if (b < 6400) {                               // wl1 -> fp16 codes
        float s = __fdiv_rn(__uint_as_float(g_absmax[2]), 7.0f);
        int i = b * 256 + tid;
        float4 v = ((const float4*)wl1)[i];
        ushort4 o;
        o.x = f2h(qw7f(v.x, s)); o.y = f2h(qw7f(v.y, s));
        o.z = f2h(qw7f(v.z, s)); o.w = f2h(qw7f(v.w, s));
        ((ushort4*)g_wl1h)[i] = o;
    } else if (b < 6440) {                        // wl2 int8 char4
        float s = __fdiv_rn(__uint_as_float(g_absmax[3]), 7.0f);
        int i = (b - 6400) * 256 + tid;
        float4 v = ((const float4*)wl2)[i];
        char4 o;
        o.x = (int8_t)qw7f(v.x, s); o.y = (int8_t)qw7f(v.y, s);
        o.z = (int8_t)qw7f(v.z, s); o.w = (int8_t)qw7f(v.w, s);
        ((char4*)g_wl2q)[i] = o;
    } else if (b < 6512) {                        // w2 -> swizzled mma layout
        float s = __fdiv_rn(__uint_as_float(g_absmax[1]), 7.0f);
        int i = (b - 6440) * 256 + tid;           // < 18432
        int o = i / 288, rem = i % 288, ci = rem / 9, tap = rem % 9;
        int k = tap * 32 + ci;
        int p = k >> 4;
        g_w2m[o * 384 + (((p ^ (o & 7)) << 4) | (k & 15))] =
            (int8_t)qw7f(w2[i], s);
    } else if (b == 6512) {                       // w1
        float s = __fdiv_rn(__uint_as_float(g_absmax[0]), 7.0f);
        for (int i = tid; i < 288; i += 256)
            g_w1q[i] = (int8_t)qw7f(w1[i], s);
    } else {                                      // LUT build
        int i = (b - 6513) * 256 + tid;
        float s_in = ps_in[0];
        float sw1 = __fdiv_rn(__uint_as_float(g_absmax[0]), 7.0f);
        float sw2 = __fdiv_rn(__uint_as_float(g_absmax[1]), 7.0f);
        float sw3 = __fdiv_rn(__uint_as_float(g_absmax[2]), 7.0f);
        if (i < 1009) {
            float s_a1 = ps_a1[0];
            float v = (float)(i - 504) * (s_in * sw1);
            float t = rintf(__fdiv_rn(v, s_a1));
            t = fminf(fmaxf(t, 0.f), 15.f);
            float t2 = rintf(__fdiv_rn(t * s_a1, s_in));
            g_lut1[i] = (int8_t)fminf(fmaxf(t2, -8.f), 7.f);
        }
        if (i < 32257) {
            float s_a2 = ps_a2[0];
            float v = (float)(i - 16128) * (s_in * sw2);
            float t = rintf(__fdiv_rn(v, s_a2));
            t = fminf(fmaxf(t, 0.f), 15.f);
            float t2 = rintf(__fdiv_rn(t * s_a2, s_in));
            g_lut2h[i] = f2h(fminf(fmaxf(t2, -8.f), 7.f));
        }
        if (i < 179201) {
            float s_a3 = ps_a3[0];
            float v = (float)(i - 89600) * (s_in * sw3);
            float t = rintf(__fdiv_rn(v, s_a3));
            g_lut3[i] = (int8_t)fminf(fmaxf(t, 0.f), 15.f);
        }
    }
}

// ---------------------------------------------------------------------------
// conv1: quantize x -> 3x3 conv via dp4a -> integer pool-max -> LUT.
__global__ void __launch_bounds__(256) k_conv1(const float* __restrict__ x,
                                               const float* __restrict__ ps_in) {
    __shared__ __align__(4) int8_t sx[28 * 32];
    __shared__ int swa[32][3], swb[32][3];
    __shared__ int8_t slut[1009];
    int b = blockIdx.x, tid = threadIdx.x;
    float s_in = ps_in[0];
    const float* xb = x + b * 784;
    for (int i = tid; i < 784; i += 256) {
        float t = rintf(__fdiv_rn(xb[i], s_in));
        t = fminf(fmaxf(t, -8.f), 7.f);
        sx[(i / 28) * 32 + (i % 28)] = (int8_t)t;
    }
    if (tid < 96) {
        int c = tid / 3, ky = tid % 3;
        int w0 = (int)g_w1q[c * 9 + ky * 3] & 0xff;
        int w1 = (int)g_w1q[c * 9 + ky * 3 + 1] & 0xff;
        int w2 = (int)g_w1q[c * 9 + ky * 3 + 2] & 0xff;
        swa[c][ky] = w0 | (w1 << 8) | (w2 << 16);
        swb[c][ky] = (w0 << 8) | (w1 << 16) | (w2 << 24);
    }
    for (int i = tid; i < 1009; i += 256) slut[i] = g_lut1[i];
    __syncthreads();

    int ch = tid & 31, wq = tid >> 5;
    int wA0 = swa[ch][0], wA1 = swa[ch][1], wA2 = swa[ch][2];
    int wB0 = swb[ch][0], wB1 = swb[ch][1], wB2 = swb[ch][2];
    const int* sxw = (const int*)sx;

    for (int it = 0; it < 22; it++) {
        int win = wq + it * 8;
        if (win >= 169) break;
        int ph = win / 13, pw = win % 13;
        int bytec = 2 * pw, widx = bytec >> 2, sh = bytec & 3;
        int r0 = 2 * ph;
        int rows[4];
#pragma unroll
        for (int r = 0; r < 4; r++) {
            int u = sxw[(r0 + r) * 8 + widx];
            int v = sxw[(r0 + r) * 8 + widx + 1];
            rows[r] = sh ? __byte_perm(u, v, 0x5432) : u;
        }
        int a00 = __dp4a(rows[0], wA0, __dp4a(rows[1], wA1, __dp4a(rows[2], wA2, 0)));
        int a01 = __dp4a(rows[0], wB0, __dp4a(rows[1], wB1, __dp4a(rows[2], wB2, 0)));
        int a10 = __dp4a(rows[1], wA0, __dp4a(rows[2], wA1, __dp4a(rows[3], wA2, 0)));
        int a11 = __dp4a(rows[1], wB0, __dp4a(rows[2], wB1, __dp4a(rows[3], wB2, 0)));
        int amax = max(max(a00, a01), max(a10, a11));
        g_a1[(b * 169 + win) * 32 + ch] = slut[amax + 504];
    }
}

// ---------------------------------------------------------------------------
__device__ __forceinline__ void ldm_x4(uint32_t addr, uint32_t* r) {
    asm volatile("ldmatrix.sync.aligned.m8n8.x4.shared.b16 {%0,%1,%2,%3}, [%4];"
                 : "=r"(r[0]), "=r"(r[1]), "=r"(r[2]), "=r"(r[3]) : "r"(addr));
}
__device__ __forceinline__ void mma_s8(int* c, const uint32_t* a,
                                       uint32_t b0, uint32_t b1) {
    asm volatile(
        "mma.sync.aligned.m16n8k32.row.col.s32.s8.s8.s32 "
        "{%0,%1,%2,%3}, {%4,%5,%6,%7}, {%8,%9}, {%0,%1,%2,%3};"
        : "+r"(c[0]), "+r"(c[1]), "+r"(c[2]), "+r"(c[3])
        : "r"(a[0]), "r"(a[1]), "r"(a[2]), "r"(a[3]), "r"(b0), "r"(b1));
}
__device__ __forceinline__ void mma_f16(float* c, const uint32_t* a,
                                        uint32_t b0, uint32_t b1) {
    asm volatile(
        "mma.sync.aligned.m16n8k16.row.col.f32.f16.f16.f32 "
        "{%0,%1,%2,%3}, {%4,%5,%6,%7}, {%8,%9}, {%0,%1,%2,%3};"
        : "+f"(c[0]), "+f"(c[1]), "+f"(c[2]), "+f"(c[3])
        : "r"(a[0]), "r"(a[1]), "r"(a[2]), "r"(a[3]), "r"(b0), "r"(b1));
}
#define CPASYNC16(dst, src) \
    asm volatile("cp.async.cg.shared.global [%0], [%1], 16;" \
                 :: "r"(dst), "l"(src) : "memory")
#define CP_COMMIT() asm volatile("cp.async.commit_group;" ::: "memory")

// ---------------------------------------------------------------------------
// conv2 via int8 mma (R11-proven): one image per CTA, cp.async staging.
// Epilogue now emits fp16 codes into g_a2h for the fp16 FC1.
__global__ void __launch_bounds__(256, 3) k_conv2() {
    extern __shared__ __align__(16) int8_t dyn2[];
    const uint32_t smem = (uint32_t)__cvta_generic_to_shared(dyn2);
    int b = blockIdx.x, tid = threadIdx.x;
    int lane = tid & 31, wid = tid >> 5;

    {
        const int8_t* src = g_w2m + tid * 16;
        uint32_t dst = smem + 43008 + tid * 16;
#pragma unroll
        for (int i = 0; i < 6; i++)
            CPASYNC16(dst + i * 4096, src + i * 4096);
    }
    {
        const int8_t* img = g_a1 + (size_t)b * 5408;
        for (int idx = tid; idx < 1800; idx += 256) {
            int r = idx / 18, p = idx - r * 18;
            int win = r >> 2, dp = r & 3;
            int ph = win / 5, pw = win - ph * 5;
            int tap = p >> 1, ky = tap / 3, kx = tap - ky * 3;
            int oy = 2 * ph + (dp >> 1) + ky, ox = 2 * pw + (dp & 1) + kx;
            CPASYNC16(smem + r * 384 + ((p ^ (r & 7)) << 4),
                      img + (oy * 13 + ox) * 32 + (p & 1) * 16);
        }
    }
    CP_COMMIT();
    asm volatile("cp.async.wait_group 0;" ::: "memory");
    __syncthreads();

    if (wid >= 7) return;
    int mt = wid;
    int rl = lane & 15, phh = lane >> 4;
    uint32_t smB = smem + 43008;
    int ra = mt * 16 + rl;
    uint32_t aBase = smem + ra * 384, aXor = (uint32_t)((ra & 7) << 4);
    uint32_t bBase[4], bXor[4];
#pragma unroll
    for (int bt = 0; bt < 4; bt++) {
        int rb = bt * 16 + rl;
        bBase[bt] = smB + rb * 384;
        bXor[bt] = (uint32_t)((rb & 7) << 4);
    }

    int acc[8][4];
#pragma unroll
    for (int i = 0; i < 8; i++)
#pragma unroll
        for (int j = 0; j < 4; j++) acc[i][j] = 0;

#pragma unroll
    for (int s = 0; s < 9; s++) {
        uint32_t pb = (uint32_t)((2 * s + phh) << 4);
        uint32_t af[4];
        ldm_x4(aBase + (pb ^ aXor), af);
        uint32_t bf[4][4];
#pragma unroll
        for (int bt = 0; bt < 4; bt++) ldm_x4(bBase[bt] + (pb ^ bXor[bt]), bf[bt]);
#pragma unroll
        for (int nt = 0; nt < 8; nt++)
            mma_s8(acc[nt], af, bf[nt >> 1][nt & 1], bf[nt >> 1][(nt & 1) + 2]);
    }

    int t4 = lane & 3;
    int winA = mt * 4 + (lane >> 4);
    int winB = winA + 2;
    bool st = ((lane >> 2) & 3) == 0;
    uint16_t* dst = g_a2h + (size_t)b * 1600;
#pragma unroll
    for (int nt = 0; nt < 8; nt++) {
        int m0 = acc[nt][0], m1 = acc[nt][1], m2 = acc[nt][2], m3 = acc[nt][3];
        m0 = max(m0, __shfl_xor_sync(0xffffffffu, m0, 4));
        m0 = max(m0, __shfl_xor_sync(0xffffffffu, m0, 8));
        m1 = max(m1, __shfl_xor_sync(0xffffffffu, m1, 4));
        m1 = max(m1, __shfl_xor_sync(0xffffffffu, m1, 8));
        m2 = max(m2, __shfl_xor_sync(0xffffffffu, m2, 4));
        m2 = max(m2, __shfl_xor_sync(0xffffffffu, m2, 8));
        m3 = max(m3, __shfl_xor_sync(0xffffffffu, m3, 4));
        m3 = max(m3, __shfl_xor_sync(0xffffffffu, m3, 8));
        if (st) {
            int col = nt * 8 + t4 * 2;
            if (winA < 25) {
                dst[col * 25 + winA]       = g_lut2h[m0 + 16128];
                dst[(col + 1) * 25 + winA] = g_lut2h[m1 + 16128];
            }
            if (winB < 25) {
                dst[col * 25 + winB]       = g_lut2h[m2 + 16128];
                dst[(col + 1) * 25 + winB] = g_lut2h[m3 + 16128];
            }
        }
    }
}

// ---------------------------------------------------------------------------
// FC1 via fp16 mma m16n8k16 (f32 acc, exact integers). BM=128 BN=128,
// K-chunk=64 halfs (128B rows, 8 planes, swizzle p^(r&7)), 3-stage cp.async.
// Stage layout: stage s at s*32768: A 16KB then B 16KB.  96KB smem, occ 2.
__global__ void __launch_bounds__(256, 2) k_fc1() {
    extern __shared__ __align__(16) int8_t dynf[];
    const uint32_t smem = (uint32_t)__cvta_generic_to_shared(dynf);
    int tid = threadIdx.x, lane = tid & 31, wid = tid >> 5;
    int wm = wid >> 2, wn = wid & 3;               // warp tile 64x32
    int m0 = blockIdx.y * 128, n0 = blockIdx.x * 128;

    // staging: thread -> row r = tid>>1 (0..127), half hs = tid&1 (planes 4hs..)
    int r = tid >> 1, hs = tid & 1;
    const char* aSrc = (const char*)g_a2h + (size_t)(m0 + r) * 3200 + hs * 64;
    const char* bSrc = (const char*)g_wl1h + (size_t)(n0 + r) * 3200 + hs * 64;
    uint32_t dstoff[4];
#pragma unroll
    for (int i = 0; i < 4; i++) {
        int p = hs * 4 + i;
        dstoff[i] = (uint32_t)(r * 128 + ((p ^ (r & 7)) << 4));
    }

    float acc[4][4][4];
#pragma unroll
    for (int i = 0; i < 4; i++)
#pragma unroll
        for (int j = 0; j < 4; j++)
#pragma unroll
            for (int k = 0; k < 4; k++) acc[i][j][k] = 0.f;

    // fragment address precompute
    int pb = lane >> 4;                            // plane low bit
    int rowf = (lane & 7) + ((lane >> 3) & 1) * 8;
    uint32_t aAddr[4], aXor[4], bAddr[2], bXor[2];
#pragma unroll
    for (int mt = 0; mt < 4; mt++) {
        int rr = wm * 64 + mt * 16 + rowf;
        aAddr[mt] = (uint32_t)(rr * 128);
        aXor[mt] = (uint32_t)(rr & 7);
    }
#pragma unroll
    for (int bt = 0; bt < 2; bt++) {
        int rr = wn * 32 + bt * 16 + rowf;
        bAddr[bt] = (uint32_t)(rr * 128 + 16384);
        bXor[bt] = (uint32_t)(rr & 7);
    }

    auto issue = [&](int ch, int st) {
        uint32_t base = smem + (uint32_t)(st * 32768);
        const char* ag = aSrc + ch * 128;
        const char* bg = bSrc + ch * 128;
#pragma unroll
        for (int i = 0; i < 4; i++) CPASYNC16(base + dstoff[i], ag + i * 16);
#pragma unroll
        for (int i = 0; i < 4; i++)
            CPASYNC16(base + 16384 + dstoff[i], bg + i * 16);
        CP_COMMIT();
    };
    issue(0, 0);
    issue(1, 1);

    for (int chk = 0; chk < 25; chk++) {
        if (chk < 24) asm volatile("cp.async.wait_group 1;" ::: "memory");
        else          asm volatile("cp.async.wait_group 0;" ::: "memory");
        __syncthreads();
        if (chk + 2 < 25) issue(chk + 2, (chk + 2) % 3);
        uint32_t base = smem + (uint32_t)((chk % 3) * 32768);
#pragma unroll
        for (int ks = 0; ks < 4; ks++) {
            uint32_t plane = (uint32_t)(2 * ks + pb);
            uint32_t af[4][4], bf[2][4];
#pragma unroll
            for (int mt = 0; mt < 4; mt++)
                ldm_x4(base + aAddr[mt] + ((plane ^ aXor[mt]) << 4), af[mt]);
#pragma unroll
            for (int bt = 0; bt < 2; bt++)
                ldm_x4(base + bAddr[bt] + ((plane ^ bXor[bt]) << 4), bf[bt]);
#pragma unroll
            for (int mt = 0; mt < 4; mt++)
#pragma unroll
                for (int nt = 0; nt < 4; nt++)
                    mma_f16(acc[mt][nt], af[mt],
                            bf[nt >> 1][nt & 1], bf[nt >> 1][(nt & 1) + 2]);
        }
    }

    int g = lane >> 2, t4 = lane & 3;
#pragma unroll
    for (int mt = 0; mt < 4; mt++) {
#pragma unroll
        for (int nt = 0; nt < 4; nt++) {
            int mrow = m0 + wm * 64 + mt * 16 + g;
            int ncol = n0 + wn * 32 + nt * 8 + t4 * 2;
#pragma unroll
            for (int h = 0; h < 2; h++) {
                char2 o;
                o.x = g_lut3[__float2int_rn(acc[mt][nt][2 * h]) + 89600];
                o.y = g_lut3[__float2int_rn(acc[mt][nt][2 * h + 1]) + 89600];
                *(char2*)(g_a3 + (size_t)(mrow + 8 * h) * 4096 + ncol) = o;
            }
        }
    }
}

// ---------------------------------------------------------------------------
// FC2: [1024,4096] x [10,4096]^T -> f32 out. Two images per block.
__global__ void __launch_bounds__(256) k_fc2(float* __restrict__ out,
                                             const float* __restrict__ ps_a3) {
    __shared__ int red[8][10];
    int tid = threadIdx.x;
    int half = tid >> 7, t = tid & 127;
    int b = blockIdx.x * 2 + half;
    const int* aw = (const int*)g_a3 + b * 1024;
    const int* wp = (const int*)g_wl2q;
    int acc[10];
#pragma unroll
    for (int n = 0; n < 10; n++) acc[n] = 0;
    for (int k = t; k < 1024; k += 128) {
        int a = aw[k];
#pragma unroll
        for (int n = 0; n < 10; n++) acc[n] = __dp4a(a, wp[n * 1024 + k], acc[n]);
    }
#pragma unroll
    for (int n = 0; n < 10; n++)
#pragma unroll
        for (int o = 16; o > 0; o >>= 1)
            acc[n] += __shfl_xor_sync(0xffffffffu, acc[n], o);
    if ((tid & 31) == 0) {
        int w = tid >> 5;
#pragma unroll
        for (int n = 0; n < 10; n++) red[w][n] = acc[n];
    }
    __syncthreads();
    if (t < 10) {
        int w0 = half * 4;
        int s = red[w0][t] + red[w0 + 1][t] + red[w0 + 2][t] + red[w0 + 3][t];
        float s_a3 = ps_a3[0];
        float s_w = __fdiv_rn(__uint_as_float(g_absmax[3]), 7.0f);
        out[b * 10 + t] = (float)s * (s_a3 * s_w);
    }
}

// ---------------------------------------------------------------------------
extern "C" void kernel_launch(void* const* d_in, const int* in_sizes, int n_in,
                              void* d_out, int out_size) {
    const float* x    = (const float*)d_in[0];
    const float* w1   = (const float*)d_in[1];
    const float* w2   = (const float*)d_in[2];
    const float* wl1  = (const float*)d_in[3];
    const float* wl2  = (const float*)d_in[4];
    const float* s_in = (const float*)d_in[5];
    const float* s_a1 = (const float*)d_in[6];
    const float* s_a2 = (const float*)d_in[7];
    const float* s_a3 = (const float*)d_in[8];
    float* out = (float*)d_out;
    (void)in_sizes; (void)n_in; (void)out_size;

    cudaFuncSetAttribute(k_conv2, cudaFuncAttributeMaxDynamicSharedMemorySize,
                         43008 + 24576);
    cudaFuncSetAttribute(k_fc1, cudaFuncAttributeMaxDynamicSharedMemorySize,
                         3 * 32768);

    k_absmax_all<<<1083, 256>>>(w1, w2, wl1, wl2);
    k_quant_all<<<7214, 256>>>(w1, w2, wl1, wl2, s_in, s_a1, s_a2, s_a3);
    k_conv1<<<1024, 256>>>(x, s_in);
    k_conv2<<<1024, 256, 43008 + 24576>>>();
    k_fc1<<<dim3(4096 / 128, 1024 / 128), 256, 3 * 32768>>>();
    k_fc2<<<512, 256>>>(out, s_a3);
}

// round 13
// speedup vs baseline: 1.6619x; 1.0074x over previous
#include <cuda_runtime.h>
#include <cuda_fp16.h>
#include <cstdint>

// ---------------------------------------------------------------------------
// Quantized LeNet, B=1024. conv1 dp4a, conv2 int8 implicit-GEMM mma.sync
// (ldmatrix per-lane addressing on the raw NHWC image -> no im2col),
// FC1 fp16 mma.sync m16n8k16 (f32 acc; exact: small-int operands, acc<2^24).
// Pool-max commutes with monotone quant; quant chains -> exact LUTs.
// ---------------------------------------------------------------------------

#define DEVBUF __device__ __align__(16)

__device__ unsigned g_absmax[4];                 // zero-init; atomicMax idempotent
DEVBUF int8_t   g_w1q [32 * 9];                  // [oc][tap]
DEVBUF int8_t   g_w2m [64 * 384];                // conv2 B, mma-swizzled
DEVBUF uint16_t g_wl1h[4096 * 1600];             // wl1 codes as fp16 [n][k]
DEVBUF int8_t   g_wl2q[10 * 4096];               // row-major [n][k]
DEVBUF int8_t   g_a1  [1024 * 13 * 13 * 32];     // conv1 out NHWC codes
DEVBUF uint16_t g_a2h [1024 * 1600];             // conv2 out codes as fp16
DEVBUF int8_t   g_a3  [1024 * 4096];             // fc1 out codes [0,15]
DEVBUF int8_t   g_lut1[1009];                    // conv1 acc -> code (+504)
DEVBUF uint16_t g_lut2h[32257];                  // conv2 acc -> fp16 code (+16128)
DEVBUF int8_t   g_lut3[179201];                  // fc1  acc -> code (+89600)

// ---------------------------------------------------------------------------
// abs-max with block reduction: ONE atomic per block.
__global__ void __launch_bounds__(256) k_absmax_all(
        const float* __restrict__ w1, const float* __restrict__ w2,
        const float* __restrict__ wl1, const float* __restrict__ wl2) {
    __shared__ float sred[8];
    int b = blockIdx.x, tid = threadIdx.x;
    float m = 0.f;
    int slot;
    if (b < 1024) {                               // wl1: 1638400 float4
        slot = 2;
        const float4* p = (const float4*)wl1;
        for (int i = b * 256 + tid; i < 1638400; i += 1024 * 256) {
            float4 v = p[i];
            m = fmaxf(m, fmaxf(fmaxf(fabsf(v.x), fabsf(v.y)),
                               fmaxf(fabsf(v.z), fabsf(v.w))));
        }
    } else if (b < 1064) {                        // wl2
        slot = 3;
        float4 v = ((const float4*)wl2)[(b - 1024) * 256 + tid];
        m = fmaxf(fmaxf(fabsf(v.x), fabsf(v.y)), fmaxf(fabsf(v.z), fabsf(v.w)));
    } else if (b < 1082) {                        // w2
        slot = 1;
        float4 v = ((const float4*)w2)[(b - 1064) * 256 + tid];
        m = fmaxf(fmaxf(fabsf(v.x), fabsf(v.y)), fmaxf(fabsf(v.z), fabsf(v.w)));
    } else {                                      // w1
        slot = 0;
        if (tid < 72) {
            float4 v = ((const float4*)w1)[tid];
            m = fmaxf(fmaxf(fabsf(v.x), fabsf(v.y)),
                      fmaxf(fabsf(v.z), fabsf(v.w)));
        }
    }
#pragma unroll
    for (int o = 16; o > 0; o >>= 1)
        m = fmaxf(m, __shfl_xor_sync(0xffffffffu, m, o));
    if ((tid & 31) == 0) sred[tid >> 5] = m;
    __syncthreads();
    if (tid == 0) {
        float r = sred[0];
#pragma unroll
        for (int w = 1; w < 8; w++) r = fmaxf(r, sred[w]);
        atomicMax(&g_absmax[slot], __float_as_uint(r));
    }
}

__device__ __forceinline__ float qw7f(float x, float s) {
    float t = rintf(__fdiv_rn(x, s));
    return fminf(fmaxf(t, -7.f), 7.f);
}
__device__ __forceinline__ uint16_t f2h(float f) {
    return __half_as_ushort(__float2half_rn(f));  // exact for small ints
}

// Weight quant + w2 mma-relayout + LUT build, one kernel.
__global__ void __launch_bounds__(256) k_quant_all(
        const float* __restrict__ w1, const float* __restrict__ w2,
        const float* __restrict__ wl1, const float* __restrict__ wl2,
        const float* __restrict__ ps_in, const float* __restrict__ ps_a1,
        const float* __restrict__ ps_a2, const float* __restrict__ ps_a3) {
    int b = blockIdx.x, tid = threadIdx.x;
    if (b < 6400) {                               // wl1 -> fp16 codes
        float s = __fdiv_rn(__uint_as_float(g_absmax[2]), 7.0f);
        int i = b * 256 + tid;
        float4 v = ((const float4*)wl1)[i];
        ushort4 o;
        o.x = f2h(qw7f(v.x, s)); o.y = f2h(qw7f(v.y, s));
        o.z = f2h(qw7f(v.z, s)); o.w = f2h(qw7f(v.w, s));
        ((ushort4*)g_wl1h)[i] = o;
    } else if (b < 6440) {                        // wl2 int8 char4
        float s = __fdiv_rn(__uint_as_float(g_absmax[3]), 7.0f);
        int i = (b - 6400) * 256 + tid;
        float4 v = ((const float4*)wl2)[i];
        char4 o;
        o.x = (int8_t)qw7f(v.x, s); o.y = (int8_t)qw7f(v.y, s);
        o.z = (int8_t)qw7f(v.z, s); o.w = (int8_t)qw7f(v.w, s);
        ((char4*)g_wl2q)[i] = o;
    } else if (b < 6512) {                        // w2 -> swizzled mma layout
        float s = __fdiv_rn(__uint_as_float(g_absmax[1]), 7.0f);
        int i = (b - 6440) * 256 + tid;           // < 18432
        int o = i / 288, rem = i % 288, ci = rem / 9, tap = rem % 9;
        int k = tap * 32 + ci;
        int p = k >> 4;
        g_w2m[o * 384 + (((p ^ (o & 7)) << 4) | (k & 15))] =
            (int8_t)qw7f(w2[i], s);
    } else if (b == 6512) {                       // w1
        float s = __fdiv_rn(__uint_as_float(g_absmax[0]), 7.0f);
        for (int i = tid; i < 288; i += 256)
            g_w1q[i] = (int8_t)qw7f(w1[i], s);
    } else {                                      // LUT build
        int i = (b - 6513) * 256 + tid;
        float s_in = ps_in[0];
        float sw1 = __fdiv_rn(__uint_as_float(g_absmax[0]), 7.0f);
        float sw2 = __fdiv_rn(__uint_as_float(g_absmax[1]), 7.0f);
        float sw3 = __fdiv_rn(__uint_as_float(g_absmax[2]), 7.0f);
        if (i < 1009) {
            float s_a1 = ps_a1[0];
            float v = (float)(i - 504) * (s_in * sw1);
            float t = rintf(__fdiv_rn(v, s_a1));
            t = fminf(fmaxf(t, 0.f), 15.f);
            float t2 = rintf(__fdiv_rn(t * s_a1, s_in));
            g_lut1[i] = (int8_t)fminf(fmaxf(t2, -8.f), 7.f);
        }
        if (i < 32257) {
            float s_a2 = ps_a2[0];
            float v = (float)(i - 16128) * (s_in * sw2);
            float t = rintf(__fdiv_rn(v, s_a2));
            t = fminf(fmaxf(t, 0.f), 15.f);
            float t2 = rintf(__fdiv_rn(t * s_a2, s_in));
            g_lut2h[i] = f2h(fminf(fmaxf(t2, -8.f), 7.f));
        }
        if (i < 179201) {
            float s_a3 = ps_a3[0];
            float v = (float)(i - 89600) * (s_in * sw3);
            float t = rintf(__fdiv_rn(v, s_a3));
            g_lut3[i] = (int8_t)fminf(fmaxf(t, 0.f), 15.f);
        }
    }
}

// ---------------------------------------------------------------------------
// conv1: quantize x -> 3x3 conv via dp4a -> integer pool-max -> LUT.
__global__ void __launch_bounds__(256) k_conv1(const float* __restrict__ x,
                                               const float* __restrict__ ps_in) {
    __shared__ __align__(4) int8_t sx[28 * 32];
    __shared__ int swa[32][3], swb[32][3];
    __shared__ int8_t slut[1009];
    int b = blockIdx.x, tid = threadIdx.x;
    float s_in = ps_in[0];
    const float* xb = x + b * 784;
    for (int i = tid; i < 784; i += 256) {
        float t = rintf(__fdiv_rn(xb[i], s_in));
        t = fminf(fmaxf(t, -8.f), 7.f);
        sx[(i / 28) * 32 + (i % 28)] = (int8_t)t;
    }
    if (tid < 96) {
        int c = tid / 3, ky = tid % 3;
        int w0 = (int)g_w1q[c * 9 + ky * 3] & 0xff;
        int w1 = (int)g_w1q[c * 9 + ky * 3 + 1] & 0xff;
        int w2 = (int)g_w1q[c * 9 + ky * 3 + 2] & 0xff;
        swa[c][ky] = w0 | (w1 << 8) | (w2 << 16);
        swb[c][ky] = (w0 << 8) | (w1 << 16) | (w2 << 24);
    }
    for (int i = tid; i < 1009; i += 256) slut[i] = g_lut1[i];
    __syncthreads();

    int ch = tid & 31, wq = tid >> 5;
    int wA0 = swa[ch][0], wA1 = swa[ch][1], wA2 = swa[ch][2];
    int wB0 = swb[ch][0], wB1 = swb[ch][1], wB2 = swb[ch][2];
    const int* sxw = (const int*)sx;

    for (int it = 0; it < 22; it++) {
        int win = wq + it * 8;
        if (win >= 169) break;
        int ph = win / 13, pw = win % 13;
        int bytec = 2 * pw, widx = bytec >> 2, sh = bytec & 3;
        int r0 = 2 * ph;
        int rows[4];
#pragma unroll
        for (int r = 0; r < 4; r++) {
            int u = sxw[(r0 + r) * 8 + widx];
            int v = sxw[(r0 + r) * 8 + widx + 1];
            rows[r] = sh ? __byte_perm(u, v, 0x5432) : u;
        }
        int a00 = __dp4a(rows[0], wA0, __dp4a(rows[1], wA1, __dp4a(rows[2], wA2, 0)));
        int a01 = __dp4a(rows[0], wB0, __dp4a(rows[1], wB1, __dp4a(rows[2], wB2, 0)));
        int a10 = __dp4a(rows[1], wA0, __dp4a(rows[2], wA1, __dp4a(rows[3], wA2, 0)));
        int a11 = __dp4a(rows[1], wB0, __dp4a(rows[2], wB1, __dp4a(rows[3], wB2, 0)));
        int amax = max(max(a00, a01), max(a10, a11));
        g_a1[(b * 169 + win) * 32 + ch] = slut[amax + 504];
    }
}

// ---------------------------------------------------------------------------
__device__ __forceinline__ void ldm_x4(uint32_t addr, uint32_t* r) {
    asm volatile("ldmatrix.sync.aligned.m8n8.x4.shared.b16 {%0,%1,%2,%3}, [%4];"
                 : "=r"(r[0]), "=r"(r[1]), "=r"(r[2]), "=r"(r[3]) : "r"(addr));
}
__device__ __forceinline__ void mma_s8(int* c, const uint32_t* a,
                                       uint32_t b0, uint32_t b1) {
    asm volatile(
        "mma.sync.aligned.m16n8k32.row.col.s32.s8.s8.s32 "
        "{%0,%1,%2,%3}, {%4,%5,%6,%7}, {%8,%9}, {%0,%1,%2,%3};"
        : "+r"(c[0]), "+r"(c[1]), "+r"(c[2]), "+r"(c[3])
        : "r"(a[0]), "r"(a[1]), "r"(a[2]), "r"(a[3]), "r"(b0), "r"(b1));
}
__device__ __forceinline__ void mma_f16(float* c, const uint32_t* a,
                                        uint32_t b0, uint32_t b1) {
    asm volatile(
        "mma.sync.aligned.m16n8k16.row.col.f32.f16.f16.f32 "
        "{%0,%1,%2,%3}, {%4,%5,%6,%7}, {%8,%9}, {%0,%1,%2,%3};"
        : "+f"(c[0]), "+f"(c[1]), "+f"(c[2]), "+f"(c[3])
        : "r"(a[0]), "r"(a[1]), "r"(a[2]), "r"(a[3]), "r"(b0), "r"(b1));
}
#define CPASYNC16(dst, src) \
    asm volatile("cp.async.cg.shared.global [%0], [%1], 16;" \
                 :: "r"(dst), "l"(src) : "memory")
#define CP_COMMIT() asm volatile("cp.async.commit_group;" ::: "memory")

// ---------------------------------------------------------------------------
// conv2 implicit-GEMM: raw NHWC image (5408B) in smem, no im2col. Per-lane
// ldmatrix row address = window position; tap = constant offset (ky*13+kx)*32.
// B = g_w2m [64 x 288] swizzled at +5504. Pool via shfl-max, LUT -> fp16.
__global__ void __launch_bounds__(256, 4) k_conv2() {
    extern __shared__ __align__(128) int8_t dyn2[];
    const uint32_t smem = (uint32_t)__cvta_generic_to_shared(dyn2);
    int b = blockIdx.x, tid = threadIdx.x;
    int lane = tid & 31, wid = tid >> 5;

    {   // stage B: 1536 16B segs, 6/thread
        const int8_t* src = g_w2m + tid * 16;
        uint32_t dst = smem + 5504 + tid * 16;
#pragma unroll
        for (int i = 0; i < 6; i++)
            CPASYNC16(dst + i * 4096, src + i * 4096);
    }
    {   // stage raw image: 338 16B segs
        const int8_t* img = g_a1 + (size_t)b * 5408;
        for (int i = tid; i < 338; i += 256)
            CPASYNC16(smem + i * 16, img + i * 16);
    }
    CP_COMMIT();
    asm volatile("cp.async.wait_group 0;" ::: "memory");
    __syncthreads();

    if (wid >= 7) return;
    int mt = wid;
    int rl = lane & 15, phh = lane >> 4;
    // per-lane A address: fragment row r -> window (win,dp) -> image (y0,x0)
    int r = mt * 16 + rl;
    int win = r >> 2, dp = r & 3;
    int ph = win / 5, pw = win - ph * 5;
    int y0 = 2 * ph + (dp >> 1), x0 = 2 * pw + (dp & 1);
    uint32_t aBase = smem + (uint32_t)((y0 * 13 + x0) * 32 + phh * 16);

    uint32_t smB = smem + 5504;
    uint32_t bBase[4], bXor[4];
#pragma unroll
    for (int bt = 0; bt < 4; bt++) {
        int rb = bt * 16 + rl;
        bBase[bt] = smB + rb * 384;
        bXor[bt] = (uint32_t)((rb & 7) << 4);
    }

    int acc[8][4];
#pragma unroll
    for (int i = 0; i < 8; i++)
#pragma unroll
        for (int j = 0; j < 4; j++) acc[i][j] = 0;

    const int tapOff[9] = {0, 32, 64, 416, 448, 480, 832, 864, 896};
#pragma unroll
    for (int s = 0; s < 9; s++) {
        uint32_t af[4];
        ldm_x4(aBase + tapOff[s], af);
        uint32_t pb = (uint32_t)((2 * s + phh) << 4);
        uint32_t bf[4][4];
#pragma unroll
        for (int bt = 0; bt < 4; bt++) ldm_x4(bBase[bt] + (pb ^ bXor[bt]), bf[bt]);
#pragma unroll
        for (int nt = 0; nt < 8; nt++)
            mma_s8(acc[nt], af, bf[nt >> 1][nt & 1], bf[nt >> 1][(nt & 1) + 2]);
    }

    int t4 = lane & 3;
    int winA = mt * 4 + (lane >> 4);
    int winB = winA + 2;
    bool st = ((lane >> 2) & 3) == 0;
    uint16_t* dst = g_a2h + (size_t)b * 1600;
#pragma unroll
    for (int nt = 0; nt < 8; nt++) {
        int m0 = acc[nt][0], m1 = acc[nt][1], m2 = acc[nt][2], m3 = acc[nt][3];
        m0 = max(m0, __shfl_xor_sync(0xffffffffu, m0, 4));
        m0 = max(m0, __shfl_xor_sync(0xffffffffu, m0, 8));
        m1 = max(m1, __shfl_xor_sync(0xffffffffu, m1, 4));
        m1 = max(m1, __shfl_xor_sync(0xffffffffu, m1, 8));
        m2 = max(m2, __shfl_xor_sync(0xffffffffu, m2, 4));
        m2 = max(m2, __shfl_xor_sync(0xffffffffu, m2, 8));
        m3 = max(m3, __shfl_xor_sync(0xffffffffu, m3, 4));
        m3 = max(m3, __shfl_xor_sync(0xffffffffu, m3, 8));
        if (st) {
            int col = nt * 8 + t4 * 2;
            if (winA < 25) {
                dst[col * 25 + winA]       = g_lut2h[m0 + 16128];
                dst[(col + 1) * 25 + winA] = g_lut2h[m1 + 16128];
            }
            if (winB < 25) {
                dst[col * 25 + winB]       = g_lut2h[m2 + 16128];
                dst[(col + 1) * 25 + winB] = g_lut2h[m3 + 16128];
            }
        }
    }
}

// ---------------------------------------------------------------------------
// FC1 via fp16 mma m16n8k16 (f32 acc, exact integers). BM=128 BN=128,
// K-chunk=64 halfs (128B rows, 8 planes, swizzle p^(r&7)), 3-stage cp.async.
__global__ void __launch_bounds__(256, 2) k_fc1() {
    extern __shared__ __align__(16) int8_t dynf[];
    const uint32_t smem = (uint32_t)__cvta_generic_to_shared(dynf);
    int tid = threadIdx.x, lane = tid & 31, wid = tid >> 5;
    int wm = wid >> 2, wn = wid & 3;               // warp tile 64x32
    int m0 = blockIdx.y * 128, n0 = blockIdx.x * 128;

    int r = tid >> 1, hs = tid & 1;
    const char* aSrc = (const char*)g_a2h + (size_t)(m0 + r) * 3200 + hs * 64;
    const char* bSrc = (const char*)g_wl1h + (size_t)(n0 + r) * 3200 + hs * 64;
    uint32_t dstoff[4];
#pragma unroll
    for (int i = 0; i < 4; i++) {
        int p = hs * 4 + i;
        dstoff[i] = (uint32_t)(r * 128 + ((p ^ (r & 7)) << 4));
    }

    float acc[4][4][4];
#pragma unroll
    for (int i = 0; i < 4; i++)
#pragma unroll
        for (int j = 0; j < 4; j++)
#pragma unroll
            for (int k = 0; k < 4; k++) acc[i][j][k] = 0.f;

    int pb = lane >> 4;
    int rowf = (lane & 7) + ((lane >> 3) & 1) * 8;
    uint32_t aAddr[4], aXor[4], bAddr[2], bXor[2];
#pragma unroll
    for (int mt = 0; mt < 4; mt++) {
        int rr = wm * 64 + mt * 16 + rowf;
        aAddr[mt] = (uint32_t)(rr * 128);
        aXor[mt] = (uint32_t)(rr & 7);
    }
#pragma unroll
    for (int bt = 0; bt < 2; bt++) {
        int rr = wn * 32 + bt * 16 + rowf;
        bAddr[bt] = (uint32_t)(rr * 128 + 16384);
        bXor[bt] = (uint32_t)(rr & 7);
    }

    auto issue = [&](int ch, int st) {
        uint32_t base = smem + (uint32_t)(st * 32768);
        const char* ag = aSrc + ch * 128;
        const char* bg = bSrc + ch * 128;
#pragma unroll
        for (int i = 0; i < 4; i++) CPASYNC16(base + dstoff[i], ag + i * 16);
#pragma unroll
        for (int i = 0; i < 4; i++)
            CPASYNC16(base + 16384 + dstoff[i], bg + i * 16);
        CP_COMMIT();
    };
    issue(0, 0);
    issue(1, 1);

    for (int chk = 0; chk < 25; chk++) {
        if (chk < 24) asm volatile("cp.async.wait_group 1;" ::: "memory");
        else          asm volatile("cp.async.wait_group 0;" ::: "memory");
        __syncthreads();
        if (chk + 2 < 25) issue(chk + 2, (chk + 2) % 3);
        uint32_t base = smem + (uint32_t)((chk % 3) * 32768);
#pragma unroll
        for (int ks = 0; ks < 4; ks++) {
            uint32_t plane = (uint32_t)(2 * ks + pb);
            uint32_t af[4][4], bf[2][4];
#pragma unroll
            for (int mt = 0; mt < 4; mt++)
                ldm_x4(base + aAddr[mt] + ((plane ^ aXor[mt]) << 4), af[mt]);
#pragma unroll
            for (int bt = 0; bt < 2; bt++)
                ldm_x4(base + bAddr[bt] + ((plane ^ bXor[bt]) << 4), bf[bt]);
#pragma unroll
            for (int mt = 0; mt < 4; mt++)
#pragma unroll
                for (int nt = 0; nt < 4; nt++)
                    mma_f16(acc[mt][nt], af[mt],
                            bf[nt >> 1][nt & 1], bf[nt >> 1][(nt & 1) + 2]);
        }
    }

    int g = lane >> 2, t4 = lane & 3;
#pragma unroll
    for (int mt = 0; mt < 4; mt++) {
#pragma unroll
        for (int nt = 0; nt < 4; nt++) {
            int mrow = m0 + wm * 64 + mt * 16 + g;
            int ncol = n0 + wn * 32 + nt * 8 + t4 * 2;
#pragma unroll
            for (int h = 0; h < 2; h++) {
                char2 o;
                o.x = g_lut3[__float2int_rn(acc[mt][nt][2 * h]) + 89600];
                o.y = g_lut3[__float2int_rn(acc[mt][nt][2 * h + 1]) + 89600];
                *(char2*)(g_a3 + (size_t)(mrow + 8 * h) * 4096 + ncol) = o;
            }
        }
    }
}

// ---------------------------------------------------------------------------
// FC2: [1024,4096] x [10,4096]^T -> f32 out. Two images per block.
__global__ void __launch_bounds__(256) k_fc2(float* __restrict__ out,
                                             const float* __restrict__ ps_a3) {
    __shared__ int red[8][10];
    int tid = threadIdx.x;
    int half = tid >> 7, t = tid & 127;
    int b = blockIdx.x * 2 + half;
    const int* aw = (const int*)g_a3 + b * 1024;
    const int* wp = (const int*)g_wl2q;
    int acc[10];
#pragma unroll
    for (int n = 0; n < 10; n++) acc[n] = 0;
    for (int k = t; k < 1024; k += 128) {
        int a = aw[k];
#pragma unroll
        for (int n = 0; n < 10; n++) acc[n] = __dp4a(a, wp[n * 1024 + k], acc[n]);
    }
#pragma unroll
    for (int n = 0; n < 10; n++)
#pragma unroll
        for (int o = 16; o > 0; o >>= 1)
            acc[n] += __shfl_xor_sync(0xffffffffu, acc[n], o);
    if ((tid & 31) == 0) {
        int w = tid >> 5;
#pragma unroll
        for (int n = 0; n < 10; n++) red[w][n] = acc[n];
    }
    __syncthreads();
    if (t < 10) {
        int w0 = half * 4;
        int s = red[w0][t] + red[w0 + 1][t] + red[w0 + 2][t] + red[w0 + 3][t];
        float s_a3 = ps_a3[0];
        float s_w = __fdiv_rn(__uint_as_float(g_absmax[3]), 7.0f);
        out[b * 10 + t] = (float)s * (s_a3 * s_w);
    }
}

// ---------------------------------------------------------------------------
extern "C" void kernel_launch(void* const* d_in, const int* in_sizes, int n_in,
                              void* d_out, int out_size) {
    const float* x    = (const float*)d_in[0];
    const float* w1   = (const float*)d_in[1];
    const float* w2   = (const float*)d_in[2];
    const float* wl1  = (const float*)d_in[3];
    const float* wl2  = (const float*)d_in[4];
    const float* s_in = (const float*)d_in[5];
    const float* s_a1 = (const float*)d_in[6];
    const float* s_a2 = (const float*)d_in[7];
    const float* s_a3 = (const float*)d_in[8];
    float* out = (float*)d_out;
    (void)in_sizes; (void)n_in; (void)out_size;

    cudaFuncSetAttribute(k_conv2, cudaFuncAttributeMaxDynamicSharedMemorySize,
                         5504 + 24576);
    cudaFuncSetAttribute(k_fc1, cudaFuncAttributeMaxDynamicSharedMemorySize,
                         3 * 32768);

    k_absmax_all<<<1083, 256>>>(w1, w2, wl1, wl2);
    k_quant_all<<<7214, 256>>>(w1, w2, wl1, wl2, s_in, s_a1, s_a2, s_a3);
    k_conv1<<<1024, 256>>>(x, s_in);
    k_conv2<<<1024, 256, 5504 + 24576>>>();
    k_fc1<<<dim3(4096 / 128, 1024 / 128), 256, 3 * 32768>>>();
    k_fc2<<<512, 256>>>(out, s_a3);
}

// round 14
// speedup vs baseline: 1.8276x; 1.0997x over previous
#include <cuda_runtime.h>
#include <cuda_fp16.h>
#include <cstdint>

// ---------------------------------------------------------------------------
// Quantized LeNet, B=1024. conv1 dp4a -> fp16 codes; conv2 fp16 implicit-GEMM
// mma.sync m16n8k16 (raw NHWC fp16 image, per-lane ldmatrix addressing, no
// im2col); FC1 fp16 mma m16n8k16. All exact: small-int operands (fp16-exact),
// f32 acc < 2^24. Pool-max commutes with monotone quant; LUT epilogues.
// ---------------------------------------------------------------------------

#define DEVBUF __device__ __align__(16)

__device__ unsigned g_absmax[4];                 // zero-init; atomicMax idempotent
DEVBUF int8_t   g_w1q [32 * 9];                  // [oc][tap]
DEVBUF int8_t   g_w2h [64 * 640];                // conv2 B fp16, 640B rows, swizzled
DEVBUF uint16_t g_wl1h[4096 * 1600];             // wl1 codes as fp16 [n][k]
DEVBUF int8_t   g_wl2q[10 * 4096];               // row-major [n][k]
DEVBUF uint16_t g_a1h [1024 * 169 * 32];         // conv1 out NHWC fp16 codes
DEVBUF uint16_t g_a2h [1024 * 1600];             // conv2 out codes as fp16
DEVBUF int8_t   g_a3  [1024 * 4096];             // fc1 out codes [0,15]
DEVBUF uint16_t g_lut1h[1009];                   // conv1 acc -> fp16 code (+504)
DEVBUF uint16_t g_lut2h[32257];                  // conv2 acc -> fp16 code (+16128)
DEVBUF int8_t   g_lut3[179201];                  // fc1  acc -> code (+89600)

// ---------------------------------------------------------------------------
// abs-max with block reduction: ONE atomic per block.
__global__ void __launch_bounds__(256) k_absmax_all(
        const float* __restrict__ w1, const float* __restrict__ w2,
        const float* __restrict__ wl1, const float* __restrict__ wl2) {
    __shared__ float sred[8];
    int b = blockIdx.x, tid = threadIdx.x;
    float m = 0.f;
    int slot;
    if (b < 1024) {                               // wl1: 1638400 float4
        slot = 2;
        const float4* p = (const float4*)wl1;
        for (int i = b * 256 + tid; i < 1638400; i += 1024 * 256) {
            float4 v = p[i];
            m = fmaxf(m, fmaxf(fmaxf(fabsf(v.x), fabsf(v.y)),
                               fmaxf(fabsf(v.z), fabsf(v.w))));
        }
    } else if (b < 1064) {                        // wl2
        slot = 3;
        float4 v = ((const float4*)wl2)[(b - 1024) * 256 + tid];
        m = fmaxf(fmaxf(fabsf(v.x), fabsf(v.y)), fmaxf(fabsf(v.z), fabsf(v.w)));
    } else if (b < 1082) {                        // w2
        slot = 1;
        float4 v = ((const float4*)w2)[(b - 1064) * 256 + tid];
        m = fmaxf(fmaxf(fabsf(v.x), fabsf(v.y)), fmaxf(fabsf(v.z), fabsf(v.w)));
    } else {                                      // w1
        slot = 0;
        if (tid < 72) {
            float4 v = ((const float4*)w1)[tid];
            m = fmaxf(fmaxf(fabsf(v.x), fabsf(v.y)),
                      fmaxf(fabsf(v.z), fabsf(v.w)));
        }
    }
#pragma unroll
    for (int o = 16; o > 0; o >>= 1)
        m = fmaxf(m, __shfl_xor_sync(0xffffffffu, m, o));
    if ((tid & 31) == 0) sred[tid >> 5] = m;
    __syncthreads();
    if (tid == 0) {
        float r = sred[0];
#pragma unroll
        for (int w = 1; w < 8; w++) r = fmaxf(r, sred[w]);
        atomicMax(&g_absmax[slot], __float_as_uint(r));
    }
}

__device__ __forceinline__ float qw7f(float x, float s) {
    float t = rintf(__fdiv_rn(x, s));
    return fminf(fmaxf(t, -7.f), 7.f);
}
__device__ __forceinline__ uint16_t f2h(float f) {
    return __half_as_ushort(__float2half_rn(f));  // exact for small ints
}

// Weight quant + w2 fp16 relayout + LUT build, one kernel.
__global__ void __launch_bounds__(256) k_quant_all(
        const float* __restrict__ w1, const float* __restrict__ w2,
        const float* __restrict__ wl1, const float* __restrict__ wl2,
        const float* __restrict__ ps_in, const float* __restrict__ ps_a1,
        const float* __restrict__ ps_a2, const float* __restrict__ ps_a3) {
    int b = blockIdx.x, tid = threadIdx.x;
    if (b < 6400) {                               // wl1 -> fp16 codes
        float s = __fdiv_rn(__uint_as_float(g_absmax[2]), 7.0f);
        int i = b * 256 + tid;
        float4 v = ((const float4*)wl1)[i];
        ushort4 o;
        o.x = f2h(qw7f(v.x, s)); o.y = f2h(qw7f(v.y, s));
        o.z = f2h(qw7f(v.z, s)); o.w = f2h(qw7f(v.w, s));
        ((ushort4*)g_wl1h)[i] = o;
    } else if (b < 6440) {                        // wl2 int8 char4
        float s = __fdiv_rn(__uint_as_float(g_absmax[3]), 7.0f);
        int i = (b - 6400) * 256 + tid;
        float4 v = ((const float4*)wl2)[i];
        char4 o;
        o.x = (int8_t)qw7f(v.x, s); o.y = (int8_t)qw7f(v.y, s);
        o.z = (int8_t)qw7f(v.z, s); o.w = (int8_t)qw7f(v.w, s);
        ((char4*)g_wl2q)[i] = o;
    } else if (b < 6512) {                        // w2 -> fp16 swizzled layout
        float s = __fdiv_rn(__uint_as_float(g_absmax[1]), 7.0f);
        int i = (b - 6440) * 256 + tid;           // < 18432
        int o = i / 288, rem = i % 288, ci = rem / 9, tap = rem % 9;
        int k = tap * 32 + ci;                    // half index 0..287
        int p = k >> 3;                           // 16B plane (8 halfs)
        *(uint16_t*)(g_w2h + o * 640 + ((p ^ (o & 7)) << 4) + ((k & 7) << 1)) =
            f2h(qw7f(w2[i], s));
    } else if (b == 6512) {                       // w1
        float s = __fdiv_rn(__uint_as_float(g_absmax[0]), 7.0f);
        for (int i = tid; i < 288; i += 256)
            g_w1q[i] = (int8_t)qw7f(w1[i], s);
    } else {                                      // LUT build
        int i = (b - 6513) * 256 + tid;
        float s_in = ps_in[0];
        float sw1 = __fdiv_rn(__uint_as_float(g_absmax[0]), 7.0f);
        float sw2 = __fdiv_rn(__uint_as_float(g_absmax[1]), 7.0f);
        float sw3 = __fdiv_rn(__uint_as_float(g_absmax[2]), 7.0f);
        if (i < 1009) {
            float s_a1 = ps_a1[0];
            float v = (float)(i - 504) * (s_in * sw1);
            float t = rintf(__fdiv_rn(v, s_a1));
            t = fminf(fmaxf(t, 0.f), 15.f);
            float t2 = rintf(__fdiv_rn(t * s_a1, s_in));
            g_lut1h[i] = f2h(fminf(fmaxf(t2, -8.f), 7.f));
        }
        if (i < 32257) {
            float s_a2 = ps_a2[0];
            float v = (float)(i - 16128) * (s_in * sw2);
            float t = rintf(__fdiv_rn(v, s_a2));
            t = fminf(fmaxf(t, 0.f), 15.f);
            float t2 = rintf(__fdiv_rn(t * s_a2, s_in));
            g_lut2h[i] = f2h(fminf(fmaxf(t2, -8.f), 7.f));
        }
        if (i < 179201) {
            float s_a3 = ps_a3[0];
            float v = (float)(i - 89600) * (s_in * sw3);
            float t = rintf(__fdiv_rn(v, s_a3));
            g_lut3[i] = (int8_t)fminf(fmaxf(t, 0.f), 15.f);
        }
    }
}

// ---------------------------------------------------------------------------
// conv1: quantize x -> 3x3 conv via dp4a -> integer pool-max -> fp16 LUT.
__global__ void __launch_bounds__(256) k_conv1(const float* __restrict__ x,
                                               const float* __restrict__ ps_in) {
    __shared__ __align__(4) int8_t sx[28 * 32];
    __shared__ int swa[32][3], swb[32][3];
    __shared__ uint16_t slut[1009];
    int b = blockIdx.x, tid = threadIdx.x;
    float s_in = ps_in[0];
    const float* xb = x + b * 784;
    for (int i = tid; i < 784; i += 256) {
        float t = rintf(__fdiv_rn(xb[i], s_in));
        t = fminf(fmaxf(t, -8.f), 7.f);
        sx[(i / 28) * 32 + (i % 28)] = (int8_t)t;
    }
    if (tid < 96) {
        int c = tid / 3, ky = tid % 3;
        int w0 = (int)g_w1q[c * 9 + ky * 3] & 0xff;
        int w1 = (int)g_w1q[c * 9 + ky * 3 + 1] & 0xff;
        int w2 = (int)g_w1q[c * 9 + ky * 3 + 2] & 0xff;
        swa[c][ky] = w0 | (w1 << 8) | (w2 << 16);
        swb[c][ky] = (w0 << 8) | (w1 << 16) | (w2 << 24);
    }
    for (int i = tid; i < 1009; i += 256) slut[i] = g_lut1h[i];
    __syncthreads();

    int ch = tid & 31, wq = tid >> 5;
    int wA0 = swa[ch][0], wA1 = swa[ch][1], wA2 = swa[ch][2];
    int wB0 = swb[ch][0], wB1 = swb[ch][1], wB2 = swb[ch][2];
    const int* sxw = (const int*)sx;

    for (int it = 0; it < 22; it++) {
        int win = wq + it * 8;
        if (win >= 169) break;
        int ph = win / 13, pw = win % 13;
        int bytec = 2 * pw, widx = bytec >> 2, sh = bytec & 3;
        int r0 = 2 * ph;
        int rows[4];
#pragma unroll
        for (int r = 0; r < 4; r++) {
            int u = sxw[(r0 + r) * 8 + widx];
            int v = sxw[(r0 + r) * 8 + widx + 1];
            rows[r] = sh ? __byte_perm(u, v, 0x5432) : u;
        }
        int a00 = __dp4a(rows[0], wA0, __dp4a(rows[1], wA1, __dp4a(rows[2], wA2, 0)));
        int a01 = __dp4a(rows[0], wB0, __dp4a(rows[1], wB1, __dp4a(rows[2], wB2, 0)));
        int a10 = __dp4a(rows[1], wA0, __dp4a(rows[2], wA1, __dp4a(rows[3], wA2, 0)));
        int a11 = __dp4a(rows[1], wB0, __dp4a(rows[2], wB1, __dp4a(rows[3], wB2, 0)));
        int amax = max(max(a00, a01), max(a10, a11));
        g_a1h[(b * 169 + win) * 32 + ch] = slut[amax + 504];
    }
}

// ---------------------------------------------------------------------------
__device__ __forceinline__ void ldm_x4(uint32_t addr, uint32_t* r) {
    asm volatile("ldmatrix.sync.aligned.m8n8.x4.shared.b16 {%0,%1,%2,%3}, [%4];"
                 : "=r"(r[0]), "=r"(r[1]), "=r"(r[2]), "=r"(r[3]) : "r"(addr));
}
__device__ __forceinline__ void mma_f16(float* c, const uint32_t* a,
                                        uint32_t b0, uint32_t b1) {
    asm volatile(
        "mma.sync.aligned.m16n8k16.row.col.f32.f16.f16.f32 "
        "{%0,%1,%2,%3}, {%4,%5,%6,%7}, {%8,%9}, {%0,%1,%2,%3};"
        : "+f"(c[0]), "+f"(c[1]), "+f"(c[2]), "+f"(c[3])
        : "r"(a[0]), "r"(a[1]), "r"(a[2]), "r"(a[3]), "r"(b0), "r"(b1));
}
#define CPASYNC16(dst, src) \
    asm volatile("cp.async.cg.shared.global [%0], [%1], 16;" \
                 :: "r"(dst), "l"(src) : "memory")
#define CP_COMMIT() asm volatile("cp.async.commit_group;" ::: "memory")

// ---------------------------------------------------------------------------
// conv2 fp16 implicit-GEMM: raw NHWC fp16 image in smem at pixel stride 80B
// (near-conflict-free A ldmatrix); B = g_w2h [64 x 640B rows] plane-swizzled.
// 18 k-steps (9 taps x 2). Pool via shfl-max on f32, LUT -> fp16.
// smem: IMG @0 (13568 = 169*80 pad), B @13568 (40960). Total 54528, occ 4.
__global__ void __launch_bounds__(256, 4) k_conv2() {
    extern __shared__ __align__(128) int8_t dyn2[];
    const uint32_t smem = (uint32_t)__cvta_generic_to_shared(dyn2);
    int b = blockIdx.x, tid = threadIdx.x;
    int lane = tid & 31, wid = tid >> 5;

    {   // stage B: 2560 16B segs, 10/thread
        const int8_t* src = g_w2h + tid * 16;
        uint32_t dst = smem + 13568 + tid * 16;
#pragma unroll
        for (int i = 0; i < 10; i++)
            CPASYNC16(dst + i * 4096, src + i * 4096);
    }
    {   // stage image: 676 segs, stride conversion 64B/pixel -> 80B/pixel
        const int8_t* img = (const int8_t*)g_a1h + (size_t)b * 10816;
        for (int i = tid; i < 676; i += 256) {
            int pix = i >> 2, pl = i & 3;
            CPASYNC16(smem + pix * 80 + pl * 16, img + i * 16);
        }
    }
    CP_COMMIT();
    asm volatile("cp.async.wait_group 0;" ::: "memory");
    __syncthreads();

    if (wid >= 7) return;
    int rl = lane & 15, pb = lane >> 4;
    int r = wid * 16 + rl;
    int win = r >> 2, dp = r & 3;
    int ph = win / 5, pw = win - ph * 5;
    int y0 = 2 * ph + (dp >> 1), x0 = 2 * pw + (dp & 1);
    uint32_t aBase = smem + (uint32_t)((y0 * 13 + x0) * 80 + pb * 16);

    uint32_t smB = smem + 13568;
    uint32_t bBase[4], bXor[4];
#pragma unroll
    for (int bt = 0; bt < 4; bt++) {
        int rb = bt * 16 + rl;
        bBase[bt] = smB + rb * 640;
        bXor[bt] = (uint32_t)(rb & 7);
    }

    float acc[8][4];
#pragma unroll
    for (int i = 0; i < 8; i++)
#pragma unroll
        for (int j = 0; j < 4; j++) acc[i][j] = 0.f;

    const int tapOff80[9] = {0, 80, 160, 1040, 1120, 1200, 2080, 2160, 2240};
#pragma unroll
    for (int ks = 0; ks < 18; ks++) {
        int s = ks >> 1, kk = ks & 1;
        uint32_t af[4];
        ldm_x4(aBase + tapOff80[s] + kk * 32, af);
        uint32_t pl = (uint32_t)(2 * ks + pb);
        uint32_t bf[4][4];
#pragma unroll
        for (int bt = 0; bt < 4; bt++)
            ldm_x4(bBase[bt] + ((pl ^ bXor[bt]) << 4), bf[bt]);
#pragma unroll
        for (int nt = 0; nt < 8; nt++)
            mma_f16(acc[nt], af, bf[nt >> 1][nt & 1], bf[nt >> 1][(nt & 1) + 2]);
    }

    int t4 = lane & 3;
    int winA = wid * 4 + (lane >> 4);
    int winB = winA + 2;
    bool st = ((lane >> 2) & 3) == 0;
    uint16_t* dst = g_a2h + (size_t)b * 1600;
#pragma unroll
    for (int nt = 0; nt < 8; nt++) {
        float m0 = acc[nt][0], m1 = acc[nt][1], m2 = acc[nt][2], m3 = acc[nt][3];
        m0 = fmaxf(m0, __shfl_xor_sync(0xffffffffu, m0, 4));
        m0 = fmaxf(m0, __shfl_xor_sync(0xffffffffu, m0, 8));
        m1 = fmaxf(m1, __shfl_xor_sync(0xffffffffu, m1, 4));
        m1 = fmaxf(m1, __shfl_xor_sync(0xffffffffu, m1, 8));
        m2 = fmaxf(m2, __shfl_xor_sync(0xffffffffu, m2, 4));
        m2 = fmaxf(m2, __shfl_xor_sync(0xffffffffu, m2, 8));
        m3 = fmaxf(m3, __shfl_xor_sync(0xffffffffu, m3, 4));
        m3 = fmaxf(m3, __shfl_xor_sync(0xffffffffu, m3, 8));
        if (st) {
            int col = nt * 8 + t4 * 2;
            if (winA < 25) {
                dst[col * 25 + winA]       = g_lut2h[__float2int_rn(m0) + 16128];
                dst[(col + 1) * 25 + winA] = g_lut2h[__float2int_rn(m1) + 16128];
            }
            if (winB < 25) {
                dst[col * 25 + winB]       = g_lut2h[__float2int_rn(m2) + 16128];
                dst[(col + 1) * 25 + winB] = g_lut2h[__float2int_rn(m3) + 16128];
            }
        }
    }
}

// ---------------------------------------------------------------------------
// FC1 via fp16 mma m16n8k16 (f32 acc, exact integers). BM=128 BN=128,
// K-chunk=64 halfs (128B rows, 8 planes, swizzle p^(r&7)), 3-stage cp.async.
__global__ void __launch_bounds__(256, 2) k_fc1() {
    extern __shared__ __align__(16) int8_t dynf[];
    const uint32_t smem = (uint32_t)__cvta_generic_to_shared(dynf);
    int tid = threadIdx.x, lane = tid & 31, wid = tid >> 5;
    int wm = wid >> 2, wn = wid & 3;               // warp tile 64x32
    int m0 = blockIdx.y * 128, n0 = blockIdx.x * 128;

    int r = tid >> 1, hs = tid & 1;
    const char* aSrc = (const char*)g_a2h + (size_t)(m0 + r) * 3200 + hs * 64;
    const char* bSrc = (const char*)g_wl1h + (size_t)(n0 + r) * 3200 + hs * 64;
    uint32_t dstoff[4];
#pragma unroll
    for (int i = 0; i < 4; i++) {
        int p = hs * 4 + i;
        dstoff[i] = (uint32_t)(r * 128 + ((p ^ (r & 7)) << 4));
    }

    float acc[4][4][4];
#pragma unroll
    for (int i = 0; i < 4; i++)
#pragma unroll
        for (int j = 0; j < 4; j++)
#pragma unroll
            for (int k = 0; k < 4; k++) acc[i][j][k] = 0.f;

    int pb = lane >> 4;
    int rowf = lane & 15;
    uint32_t aAddr[4], aXor[4], bAddr[2], bXor[2];
#pragma unroll
    for (int mt = 0; mt < 4; mt++) {
        int rr = wm * 64 + mt * 16 + rowf;
        aAddr[mt] = (uint32_t)(rr * 128);
        aXor[mt] = (uint32_t)(rr & 7);
    }
#pragma unroll
    for (int bt = 0; bt < 2; bt++) {
        int rr = wn * 32 + bt * 16 + rowf;
        bAddr[bt] = (uint32_t)(rr * 128 + 16384);
        bXor[bt] = (uint32_t)(rr & 7);
    }

    auto issue = [&](int ch, int st) {
        uint32_t base = smem + (uint32_t)(st * 32768);
        const char* ag = aSrc + ch * 128;
        const char* bg = bSrc + ch * 128;
#pragma unroll
        for (int i = 0; i < 4; i++) CPASYNC16(base + dstoff[i], ag + i * 16);
#pragma unroll
        for (int i = 0; i < 4; i++)
            CPASYNC16(base + 16384 + dstoff[i], bg + i * 16);
        CP_COMMIT();
    };
    issue(0, 0);
    issue(1, 1);

    for (int chk = 0; chk < 25; chk++) {
        if (chk < 24) asm volatile("cp.async.wait_group 1;" ::: "memory");
        else          asm volatile("cp.async.wait_group 0;" ::: "memory");
        __syncthreads();
        if (chk + 2 < 25) issue(chk + 2, (chk + 2) % 3);
        uint32_t base = smem + (uint32_t)((chk % 3) * 32768);
#pragma unroll
        for (int ks = 0; ks < 4; ks++) {
            uint32_t plane = (uint32_t)(2 * ks + pb);
            uint32_t af[4][4], bf[2][4];
#pragma unroll
            for (int mt = 0; mt < 4; mt++)
                ldm_x4(base + aAddr[mt] + ((plane ^ aXor[mt]) << 4), af[mt]);
#pragma unroll
            for (int bt = 0; bt < 2; bt++)
                ldm_x4(base + bAddr[bt] + ((plane ^ bXor[bt]) << 4), bf[bt]);
#pragma unroll
            for (int mt = 0; mt < 4; mt++)
#pragma unroll
                for (int nt = 0; nt < 4; nt++)
                    mma_f16(acc[mt][nt], af[mt],
                            bf[nt >> 1][nt & 1], bf[nt >> 1][(nt & 1) + 2]);
        }
    }

    int g = lane >> 2, t4 = lane & 3;
#pragma unroll
    for (int mt = 0; mt < 4; mt++) {
#pragma unroll
        for (int nt = 0; nt < 4; nt++) {
            int mrow = m0 + wm * 64 + mt * 16 + g;
            int ncol = n0 + wn * 32 + nt * 8 + t4 * 2;
#pragma unroll
            for (int h = 0; h < 2; h++) {
                char2 o;
                o.x = g_lut3[__float2int_rn(acc[mt][nt][2 * h]) + 89600];
                o.y = g_lut3[__float2int_rn(acc[mt][nt][2 * h + 1]) + 89600];
                *(char2*)(g_a3 + (size_t)(mrow + 8 * h) * 4096 + ncol) = o;
            }
        }
    }
}

// ---------------------------------------------------------------------------
// FC2: [1024,4096] x [10,4096]^T -> f32 out. Two images per block.
__global__ void __launch_bounds__(256) k_fc2(float* __restrict__ out,
                                             const float* __restrict__ ps_a3) {
    __shared__ int red[8][10];
    int tid = threadIdx.x;
    int half = tid >> 7, t = tid & 127;
    int b = blockIdx.x * 2 + half;
    const int* aw = (const int*)g_a3 + b * 1024;
    const int* wp = (const int*)g_wl2q;
    int acc[10];
#pragma unroll
    for (int n = 0; n < 10; n++) acc[n] = 0;
    for (int k = t; k < 1024; k += 128) {
        int a = aw[k];
#pragma unroll
        for (int n = 0; n < 10; n++) acc[n] = __dp4a(a, wp[n * 1024 + k], acc[n]);
    }
#pragma unroll
    for (int n = 0; n < 10; n++)
#pragma unroll
        for (int o = 16; o > 0; o >>= 1)
            acc[n] += __shfl_xor_sync(0xffffffffu, acc[n], o);
    if ((tid & 31) == 0) {
        int w = tid >> 5;
#pragma unroll
        for (int n = 0; n < 10; n++) red[w][n] = acc[n];
    }
    __syncthreads();
    if (t < 10) {
        int w0 = half * 4;
        int s = red[w0][t] + red[w0 + 1][t] + red[w0 + 2][t] + red[w0 + 3][t];
        float s_a3 = ps_a3[0];
        float s_w = __fdiv_rn(__uint_as_float(g_absmax[3]), 7.0f);
        out[b * 10 + t] = (float)s * (s_a3 * s_w);
    }
}

// ---------------------------------------------------------------------------
extern "C" void kernel_launch(void* const* d_in, const int* in_sizes, int n_in,
                              void* d_out, int out_size) {
    const float* x    = (const float*)d_in[0];
    const float* w1   = (const float*)d_in[1];
    const float* w2   = (const float*)d_in[2];
    const float* wl1  = (const float*)d_in[3];
    const float* wl2  = (const float*)d_in[4];
    const float* s_in = (const float*)d_in[5];
    const float* s_a1 = (const float*)d_in[6];
    const float* s_a2 = (const float*)d_in[7];
    const float* s_a3 = (const float*)d_in[8];
    float* out = (float*)d_out;
    (void)in_sizes; (void)n_in; (void)out_size;

    cudaFuncSetAttribute(k_conv2, cudaFuncAttributeMaxDynamicSharedMemorySize,
                         13568 + 40960);
    cudaFuncSetAttribute(k_fc1, cudaFuncAttributeMaxDynamicSharedMemorySize,
                         3 * 32768);

    k_absmax_all<<<1083, 256>>>(w1, w2, wl1, wl2);
    k_quant_all<<<7214, 256>>>(w1, w2, wl1, wl2, s_in, s_a1, s_a2, s_a3);
    k_conv1<<<1024, 256>>>(x, s_in);
    k_conv2<<<1024, 256, 13568 + 40960>>>();
    k_fc1<<<dim3(4096 / 128, 1024 / 128), 256, 3 * 32768>>>();
    k_fc2<<<512, 256>>>(out, s_a3);
}